// round 15
// baseline (speedup 1.0000x reference)
#include <cuda_runtime.h>
#include <cuda_bf16.h>
#include <math.h>
#include <stdint.h>

#define B_   16
#define C_   256
#define HWP  4096
#define NH   8

typedef __nv_bfloat16 bf;

// ---------------- scratch ----------------
__device__ bf     g_xh [(size_t)B_ * HWP * C_];
__device__ bf     g_xl [(size_t)B_ * HWP * C_];
__device__ bf     g_xch[(size_t)B_ * C_ * HWP];
__device__ bf     g_xcl[(size_t)B_ * C_ * HWP];
__device__ float  g_XC [(size_t)B_ * C_ * 132];
__device__ float  g_Gp [(size_t)6 * B_ * C_ * C_];
__device__ float  g_U  [(size_t)B_ * C_ * C_];
__device__ float  g_MN [(size_t)B_ * 512 * 132];
__device__ float  g_Pq [(size_t)C_ * 132];
__device__ float  g_Pk [(size_t)C_ * 132];
__device__ float  g_Pk2[(size_t)C_ * 132];
__device__ bf     g_weh[(size_t)B_ * C_ * C_];
__device__ bf     g_wel[(size_t)B_ * C_ * C_];
__device__ float  g_cb [(size_t)B_ * C_];

// ---------------- helpers ----------------
__device__ __forceinline__ uint32_t smem_u32(const void* p) {
    uint32_t a;
    asm("{ .reg .u64 t; cvta.to.shared.u64 t, %1; cvt.u32.u64 %0, t; }" : "=r"(a) : "l"(p));
    return a;
}
__device__ __forceinline__ void ldsm_x4(uint32_t* r, uint32_t addr) {
    asm volatile("ldmatrix.sync.aligned.m8n8.x4.shared.b16 {%0,%1,%2,%3}, [%4];"
        : "=r"(r[0]), "=r"(r[1]), "=r"(r[2]), "=r"(r[3]) : "r"(addr));
}
__device__ __forceinline__ void mma_bf16(float* c, const uint32_t* a, const uint32_t* b) {
    asm volatile("mma.sync.aligned.m16n8k16.row.col.f32.bf16.bf16.f32 "
        "{%0,%1,%2,%3}, {%4,%5,%6,%7}, {%8,%9}, {%0,%1,%2,%3};"
        : "+f"(c[0]), "+f"(c[1]), "+f"(c[2]), "+f"(c[3])
        : "r"(a[0]), "r"(a[1]), "r"(a[2]), "r"(a[3]), "r"(b[0]), "r"(b[1]));
}
__device__ __forceinline__ float silu_f(float v) { return v / (1.0f + expf(-v)); }

// ---------------- K1: silu ----------------
__global__ __launch_bounds__(256)
void silu_split_kernel(const float* __restrict__ x, const float* __restrict__ pab,
                       const float* __restrict__ pqb, float* __restrict__ out,
                       bf* __restrict__ xh, bf* __restrict__ xl,
                       bf* __restrict__ xch, bf* __restrict__ xcl) {
    __shared__ float s[64][65];
    const int bid = blockIdx.x;
    const int p0 = (bid & 63) * 64;
    const int c0 = ((bid >> 6) & 3) * 64;
    const int b  = bid >> 8;
    const int tid = threadIdx.x;
#pragma unroll
    for (int ii = 0; ii < 4; ii++) {
        int lin = tid + ii * 256;
        int r = lin >> 4, u = lin & 15;
        float4 v = *(const float4*)(x + (size_t)(b * 256 + c0 + r) * HWP + p0 + u * 4);
        float pb = pab[c0 + r];
        float4 o;
        o.x = silu_f(v.x + pb); o.y = silu_f(v.y + pb);
        o.z = silu_f(v.z + pb); o.w = silu_f(v.w + pb);
        *(float4*)(out + (size_t)(b * 512 + c0 + r) * HWP + p0 + u * 4) = o;
        float pq = pqb[c0 + r];
        float xp[4] = {o.x + pq, o.y + pq, o.z + pq, o.w + pq};
        s[r][u * 4 + 0] = xp[0]; s[r][u * 4 + 1] = xp[1];
        s[r][u * 4 + 2] = xp[2]; s[r][u * 4 + 3] = xp[3];
        bf h[4], l[4];
#pragma unroll
        for (int j = 0; j < 4; j++) {
            h[j] = __float2bfloat16(xp[j]);
            l[j] = __float2bfloat16(xp[j] - __bfloat162float(h[j]));
        }
        size_t cbase = (size_t)(b * 256 + c0 + r) * HWP + p0 + u * 4;
        __nv_bfloat162 hh0 = {h[0], h[1]}, hh1 = {h[2], h[3]};
        __nv_bfloat162 ll0 = {l[0], l[1]}, ll1 = {l[2], l[3]};
        *(uint2*)(xch + cbase) = make_uint2(*(uint32_t*)&hh0, *(uint32_t*)&hh1);
        *(uint2*)(xcl + cbase) = make_uint2(*(uint32_t*)&ll0, *(uint32_t*)&ll1);
    }
    __syncthreads();
#pragma unroll
    for (int ii = 0; ii < 4; ii++) {
        int lin = tid + ii * 256;
        int r = lin >> 4, u = lin & 15;
        float v[4];
#pragma unroll
        for (int j = 0; j < 4; j++) v[j] = s[u * 4 + j][r];
        bf h[4], l[4];
#pragma unroll
        for (int j = 0; j < 4; j++) {
            h[j] = __float2bfloat16(v[j]);
            l[j] = __float2bfloat16(v[j] - __bfloat162float(h[j]));
        }
        size_t base = (size_t)(b * HWP + p0 + r) * C_ + c0 + u * 4;
        __nv_bfloat162 hh0 = {h[0], h[1]}, hh1 = {h[2], h[3]};
        __nv_bfloat162 ll0 = {l[0], l[1]}, ll1 = {l[2], l[3]};
        *(uint2*)(xh + base) = make_uint2(*(uint32_t*)&hh0, *(uint32_t*)&hh1);
        *(uint2*)(xl + base) = make_uint2(*(uint32_t*)&ll0, *(uint32_t*)&ll1);
    }
}

// ---------------- K2: reduceX ----------------
__global__ __launch_bounds__(256)
void reduceX(const float* __restrict__ out, const float* __restrict__ pqb,
             float* __restrict__ XC) {
    __shared__ float sm_[64][65];
    __shared__ float rs[64];
    const int e = blockIdx.x, b = blockIdx.y;
    const float4* src = (const float4*)(out + ((size_t)b * 512 + e) * HWP);
    const float pq = pqb[e];
    const int tid = threadIdx.x;
#pragma unroll
    for (int i = 0; i < 4; i++) {
        int idx = tid + i * 256;
        float4 v = src[idx];
        int y = idx >> 4, xc = (idx & 15) * 4;
        sm_[y][xc + 0] = v.x + pq; sm_[y][xc + 1] = v.y + pq;
        sm_[y][xc + 2] = v.z + pq; sm_[y][xc + 3] = v.w + pq;
    }
    __syncthreads();
    float* dst = XC + ((size_t)b * 256 + e) * 132;
    if (tid < 64) {
        float sum = 0.f;
#pragma unroll 8
        for (int xx = 0; xx < 64; xx++) sum += sm_[tid][xx];
        dst[tid] = sum;
        rs[tid] = sum;
    } else if (tid < 128) {
        int xx = tid - 64;
        float sum = 0.f;
#pragma unroll 8
        for (int y = 0; y < 64; y++) sum += sm_[y][xx];
        dst[64 + xx] = sum;
    }
    __syncthreads();
    if (tid == 0) {
        float S = 0.f;
        for (int y = 0; y < 64; y++) S += rs[y];
        dst[128] = S; dst[129] = 0.f; dst[130] = 0.f; dst[131] = 0.f;
    }
}

// ---------------- K3: prepP ----------------
__global__ __launch_bounds__(64)
void prepP(const float* __restrict__ qkv_b,
           const float* __restrict__ peqh, const float* __restrict__ peqw,
           const float* __restrict__ pekh, const float* __restrict__ pekw,
           float* __restrict__ Pq, float* __restrict__ Pk, float* __restrict__ Pk2) {
    const int i = blockIdx.x, t = threadIdx.x;
    __shared__ float red[4];
    float phq = peqh[i * 64 + t], pwq = peqw[i * 64 + t];
    float phk = pekh[i * 64 + t], pwk = pekw[i * 64 + t];
    float kb = qkv_b[256 + i];
    float h = phk, w = pwk;
#pragma unroll
    for (int o = 16; o; o >>= 1) {
        h += __shfl_xor_sync(0xffffffffu, h, o);
        w += __shfl_xor_sync(0xffffffffu, w, o);
    }
    if ((t & 31) == 0) { red[(t >> 5) * 2] = h; red[(t >> 5) * 2 + 1] = w; }
    __syncthreads();
    float Hks = red[0] + red[2], Wks = red[1] + red[3];
    Pq[i * 132 + t] = phq;       Pq[i * 132 + 64 + t] = pwq;
    Pk[i * 132 + t] = phk;       Pk[i * 132 + 64 + t] = pwk;
    Pk2[i * 132 + t]      = 64.f * kb + 64.f * phk + Wks;
    Pk2[i * 132 + 64 + t] = 64.f * kb + 64.f * pwk + Hks;
    if (t == 0) {
        Pq[i * 132 + 128] = qkv_b[i];
        Pk[i * 132 + 128] = kb;
        Pk2[i * 132 + 128] = 4096.f * kb + 64.f * Hks + 64.f * Wks;
        for (int j = 129; j < 132; j++) { Pq[i*132+j] = 0.f; Pk[i*132+j] = 0.f; Pk2[i*132+j] = 0.f; }
    }
}

// ---------------- mma split pipeline ----------------
#define KC        32
#define TILE_BYT  8192
#define GSMEM     (3 * 4 * TILE_BYT)

__device__ __forceinline__ void load_tile_sw(uint32_t sm, const bf* g, size_t ld, int tid) {
#pragma unroll
    for (int ii = 0; ii < 2; ii++) {
        int lin = tid + ii * 256;
        int r = lin >> 2, u = lin & 3;
        uint32_t dst = sm + r * 64 + ((u ^ ((r >> 1) & 3)) * 16);
        const bf* src = g + (size_t)r * ld + u * 8;
        asm volatile("cp.async.cg.shared.global [%0], [%1], 16;" :: "r"(dst), "l"(src));
    }
}

template <bool DIAG>
__device__ __forceinline__ void issue_stage(uint32_t sbase,
    const bf* gAh, const bf* gAl, const bf* gBh, const bf* gBl,
    size_t ld, int ch, int tid) {
    load_tile_sw(sbase + 0 * TILE_BYT, gAh + (size_t)ch * KC, ld, tid);
    load_tile_sw(sbase + 1 * TILE_BYT, gAl + (size_t)ch * KC, ld, tid);
    if (!DIAG) {
        load_tile_sw(sbase + 2 * TILE_BYT, gBh + (size_t)ch * KC, ld, tid);
        load_tile_sw(sbase + 3 * TILE_BYT, gBl + (size_t)ch * KC, ld, tid);
    }
    asm volatile("cp.async.commit_group;");
}

template <bool DIAG>
__device__ __forceinline__ void mma_pipeline(uint32_t ubase, int nch,
    const bf* gAh, const bf* gAl, const bf* gBh, const bf* gBl, size_t ld,
    int tid, int warp_m, int warp_n, float c[4][4][4]) {
    const uint32_t STG = (DIAG ? 2 : 4) * TILE_BYT;
    const int lane = tid & 31;
    uint32_t a_off[2], b_off[2];
    {
        const int sw  = (lane >> 1) & 3;
        const int l15 = lane & 15;
        const int rit = ((lane >> 4) << 3) + (lane & 7);
#pragma unroll
        for (int ks = 0; ks < 2; ks++) {
            a_off[ks] = (uint32_t)l15 * 64 + (uint32_t)(((ks * 2 + (lane >> 4)) ^ sw) * 16);
            b_off[ks] = (uint32_t)rit * 64 + (uint32_t)(((ks * 2 + ((lane >> 3) & 1)) ^ sw) * 16);
        }
    }

    issue_stage<DIAG>(ubase + 0 * STG, gAh, gAl, gBh, gBl, ld, 0, tid);
    issue_stage<DIAG>(ubase + 1 * STG, gAh, gAl, gBh, gBl, ld, 1, tid);

    int st = 0;
    for (int ch = 0; ch < nch; ch++) {
        if (ch < nch - 1) { asm volatile("cp.async.wait_group 1;"); }
        else              { asm volatile("cp.async.wait_group 0;"); }
        __syncthreads();
        if (ch + 2 < nch) {
            int st2 = st + 2; if (st2 >= 3) st2 -= 3;
            issue_stage<DIAG>(ubase + (uint32_t)st2 * STG,
                              gAh, gAl, gBh, gBl, ld, ch + 2, tid);
        }

        const uint32_t uAh = ubase + (uint32_t)st * STG;
        const uint32_t uAl = uAh + TILE_BYT;
        const uint32_t uBh = DIAG ? uAh : (uAh + 2 * TILE_BYT);
        const uint32_t uBl = DIAG ? uAl : (uAh + 3 * TILE_BYT);
#pragma unroll
        for (int ks = 0; ks < 2; ks++) {
            uint32_t ah[4][4], al[4][4], bh[4][2], bl[4][2];
#pragma unroll
            for (int mt = 0; mt < 4; mt++) {
                uint32_t ra = (uint32_t)(warp_m + mt * 16) * 64;
                ldsm_x4(ah[mt], uAh + ra + a_off[ks]);
                ldsm_x4(al[mt], uAl + ra + a_off[ks]);
            }
#pragma unroll
            for (int nt2 = 0; nt2 < 2; nt2++) {
                uint32_t rb = (uint32_t)(warp_n + nt2 * 16) * 64;
                uint32_t t0[4], t1[4];
                ldsm_x4(t0, uBh + rb + b_off[ks]);
                ldsm_x4(t1, uBl + rb + b_off[ks]);
                bh[nt2 * 2][0] = t0[0]; bh[nt2 * 2][1] = t0[1];
                bh[nt2 * 2 + 1][0] = t0[2]; bh[nt2 * 2 + 1][1] = t0[3];
                bl[nt2 * 2][0] = t1[0]; bl[nt2 * 2][1] = t1[1];
                bl[nt2 * 2 + 1][0] = t1[2]; bl[nt2 * 2 + 1][1] = t1[3];
            }
#pragma unroll
            for (int mt = 0; mt < 4; mt++)
#pragma unroll
                for (int nt = 0; nt < 4; nt++) mma_bf16(c[mt][nt], ah[mt], bh[nt]);
#pragma unroll
            for (int mt = 0; mt < 4; mt++)
#pragma unroll
                for (int nt = 0; nt < 4; nt++) mma_bf16(c[mt][nt], ah[mt], bl[nt]);
#pragma unroll
            for (int mt = 0; mt < 4; mt++)
#pragma unroll
                for (int nt = 0; nt < 4; nt++) mma_bf16(c[mt][nt], al[mt], bh[nt]);
        }
        if (++st == 3) st = 0;
    }
    __syncthreads();
}

// ---------------- K4: G partials ----------------
__global__ __launch_bounds__(256, 2)
void gemmG(const bf* __restrict__ xch, const bf* __restrict__ xcl,
           float* __restrict__ Gp) {
    extern __shared__ __align__(16) char dyn[];
    const uint32_t ubase = smem_u32(dyn);
    const int tile = blockIdx.x;
    const int e0 = (tile == 2) ? 128 : 0;
    const int f0 = (tile == 0) ? 0 : 128;
    const bool diag = (tile != 1);
    const int s = blockIdx.y;
    const int b = blockIdx.z;
    const int start = 21 * s + (s > 4 ? s - 4 : 0);
    const int nch   = (s < 4) ? 21 : 22;
    const int tid = threadIdx.x, wid = tid >> 5, lane = tid & 31;
    const int warp_m = (wid & 1) * 64, warp_n = (wid >> 1) * 32;

    float c[4][4][4];
#pragma unroll
    for (int i = 0; i < 4; i++)
#pragma unroll
        for (int j = 0; j < 4; j++)
#pragma unroll
            for (int q = 0; q < 4; q++) c[i][j][q] = 0.f;

    const size_t noff = (size_t)start * KC;
    const bf* gAh = xch + ((size_t)b * 256 + e0) * HWP + noff;
    const bf* gAl = xcl + ((size_t)b * 256 + e0) * HWP + noff;
    const bf* gBh = xch + ((size_t)b * 256 + f0) * HWP + noff;
    const bf* gBl = xcl + ((size_t)b * 256 + f0) * HWP + noff;

    if (diag)
        mma_pipeline<true>(ubase, nch, gAh, gAl, gBh, gBl, HWP, tid, warp_m, warp_n, c);
    else
        mma_pipeline<false>(ubase, nch, gAh, gAl, gBh, gBl, HWP, tid, warp_m, warp_n, c);

    const int g = lane >> 2, t = lane & 3;
    float* dst = Gp + (size_t)(b * 6 + s) * 65536;
#pragma unroll
    for (int mt = 0; mt < 4; mt++)
#pragma unroll
        for (int nt = 0; nt < 4; nt++) {
            int f = f0 + warp_n + nt * 8 + 2 * t;
#pragma unroll
            for (int half = 0; half < 2; half++) {
                int e = e0 + warp_m + mt * 16 + g + half * 8;
                *(float2*)&dst[(size_t)e * 256 + f] =
                    make_float2(c[mt][nt][half * 2 + 0], c[mt][nt][half * 2 + 1]);
            }
        }
}

// ---------------- K5: gemmUf — fused reduceG + U = Wq·G for one 64-col block ----------------
#define GS_STRIDE 68
__global__ __launch_bounds__(256)
void gemmUf(const float* __restrict__ Wq, const float* __restrict__ Gp,
            float* __restrict__ U) {
    extern __shared__ float Gs[];              // [256][GS_STRIDE]
    __shared__ float As[16][68];
    const int jx = blockIdx.x;                 // 0..3, j0 = 64*jx
    const int b  = blockIdx.y;
    const int j0 = jx * 64;
    const int tid = threadIdx.x;
    const bool mirrorHalf = (jx < 2);          // rows k>=128 need Gp[j][k]
    const float* GpB = Gp + (size_t)b * 6 * 65536;

    // phase 1a: normal region (k < kLim), float4 over j
    {
        const int kLim = mirrorHalf ? 128 : 256;
        const int nF4 = kLim * 16;             // float4 count
        for (int f4 = tid; f4 < nF4; f4 += 256) {
            int k = f4 >> 4, jg = (f4 & 15) * 4;
            float4 acc = make_float4(0.f, 0.f, 0.f, 0.f);
#pragma unroll
            for (int z = 0; z < 6; z++) {
                float4 v = *(const float4*)&GpB[(size_t)z * 65536 + (size_t)k * 256 + j0 + jg];
                acc.x += v.x; acc.y += v.y; acc.z += v.z; acc.w += v.w;
            }
            float* row = &Gs[k * GS_STRIDE + jg];
            row[0] = acc.x; row[1] = acc.y; row[2] = acc.z; row[3] = acc.w;
        }
    }
    // phase 1b: mirror region k in [128,256), read Gp rows j0+jl, cols k
    if (mirrorHalf) {
        const int jl = tid & 63, kq = tid >> 6;
#pragma unroll
        for (int it = 0; it < 8; it++) {
            int k4 = 128 + kq * 32 + it * 4;
            float4 acc = make_float4(0.f, 0.f, 0.f, 0.f);
#pragma unroll
            for (int z = 0; z < 6; z++) {
                float4 v = *(const float4*)&GpB[(size_t)z * 65536 + (size_t)(j0 + jl) * 256 + k4];
                acc.x += v.x; acc.y += v.y; acc.z += v.z; acc.w += v.w;
            }
            Gs[(k4 + 0) * GS_STRIDE + jl] = acc.x;
            Gs[(k4 + 1) * GS_STRIDE + jl] = acc.y;
            Gs[(k4 + 2) * GS_STRIDE + jl] = acc.z;
            Gs[(k4 + 3) * GS_STRIDE + jl] = acc.w;
        }
    }
    __syncthreads();

    // phase 2: U[i0.., j-block] = Wq · Gs
    const int ty = tid >> 4, tx = tid & 15;
#pragma unroll 1
    for (int i0 = 0; i0 < 256; i0 += 64) {
        float acc[4][4] = {};
        for (int k0 = 0; k0 < 256; k0 += 16) {
            {
                int i = tid >> 2, k4 = (tid & 3) * 4;
                float4 a = *(const float4*)&Wq[(size_t)(i0 + i) * 256 + k0 + k4];
                As[k4 + 0][i] = a.x; As[k4 + 1][i] = a.y;
                As[k4 + 2][i] = a.z; As[k4 + 3][i] = a.w;
            }
            __syncthreads();
#pragma unroll
            for (int k = 0; k < 16; k++) {
                float a[4], bb[4];
#pragma unroll
                for (int x = 0; x < 4; x++) a[x] = As[k][ty * 4 + x];
#pragma unroll
                for (int x = 0; x < 4; x++) bb[x] = Gs[(k0 + k) * GS_STRIDE + tx * 4 + x];
#pragma unroll
                for (int ii = 0; ii < 4; ii++)
#pragma unroll
                    for (int jj = 0; jj < 4; jj++) acc[ii][jj] += a[ii] * bb[jj];
            }
            __syncthreads();
        }
#pragma unroll
        for (int ii = 0; ii < 4; ii++)
            *(float4*)&U[((size_t)b * 256 + i0 + ty * 4 + ii) * 256 + j0 + tx * 4] =
                make_float4(acc[ii][0], acc[ii][1], acc[ii][2], acc[ii][3]);
    }
}

// ---------------- K7: gemmMAN ----------------
__global__ __launch_bounds__(256)
void gemmMAN(const float* __restrict__ qkv_w, const float* __restrict__ XC,
             float* __restrict__ MN) {
    __shared__ float Ws[32][36];
    __shared__ float XCs[32][132];
    const int r0 = blockIdx.x * 32;
    const int b  = blockIdx.y;
    const int tid = threadIdx.x;
    const int w   = tid >> 5;
    const int lane = tid & 31;
    float acc[4][5];
#pragma unroll
    for (int i = 0; i < 4; i++)
#pragma unroll
        for (int cg = 0; cg < 5; cg++) acc[i][cg] = 0.f;
    const bool has5 = (lane < 4);

    for (int k0 = 0; k0 < 256; k0 += 32) {
        {
            int r = tid >> 3, k4 = (tid & 7) * 4;
            *(float4*)&Ws[r][k4] = *(const float4*)&qkv_w[(size_t)(r0 + r) * 256 + k0 + k4];
        }
#pragma unroll
        for (int it = 0; it < 5; it++) {
            int f4 = tid + it * 256;
            if (f4 < 1056) {
                int k = f4 / 33, g = f4 % 33;
                *(float4*)&XCs[k][g * 4] =
                    *(const float4*)&XC[((size_t)b * 256 + k0 + k) * 132 + g * 4];
            }
        }
        __syncthreads();
#pragma unroll 4
        for (int k = 0; k < 32; k++) {
            float xv[5];
#pragma unroll
            for (int cg = 0; cg < 4; cg++) xv[cg] = XCs[k][lane + 32 * cg];
            xv[4] = has5 ? XCs[k][lane + 128] : 0.f;
#pragma unroll
            for (int i = 0; i < 4; i++) {
                float wv = Ws[w * 4 + i][k];
#pragma unroll
                for (int cg = 0; cg < 5; cg++) acc[i][cg] += wv * xv[cg];
            }
        }
        __syncthreads();
    }
#pragma unroll
    for (int i = 0; i < 4; i++) {
        float* dst = MN + ((size_t)b * 512 + r0 + w * 4 + i) * 132;
#pragma unroll
        for (int cg = 0; cg < 4; cg++) dst[lane + 32 * cg] = acc[i][cg];
        if (has5) dst[lane + 128] = acc[i][4];
    }
}

// ---------------- K8: assembly (batch-offset) ----------------
#define SKS 257
#define SPS 133
__global__ __launch_bounds__(256)
void assembly(const float* __restrict__ U, const float* __restrict__ qkv_w,
              const float* __restrict__ qkv_b, const float* __restrict__ MN,
              const float* __restrict__ Pq, const float* __restrict__ Pk,
              const float* __restrict__ Pk2,
              const float* __restrict__ mod_mult, const float* __restrict__ mod_bias,
              bf* __restrict__ weh, bf* __restrict__ wel, float* __restrict__ cb, int b0) {
    extern __shared__ float sm[];
    float* sU  = sm;
    float* sK  = sU + 32 * SKS;
    float* sMA = sK + 32 * SKS;
    float* sPq = sMA + 32 * SPS;
    float* sPk = sPq + 32 * SPS;
    float* sNB2 = sPk + 32 * SPS;
    float* sL  = sNB2 + 32 * SPS;
    const int h = blockIdx.x, b = blockIdx.y + b0;
    const int ch0 = h * 32;
    const int tid = threadIdx.x;

    for (int i = tid; i < 32 * 256; i += 256) {
        int r = i >> 8, e = i & 255;
        sU[r * SKS + e] = U[((size_t)b * 256 + ch0 + r) * 256 + e];
        sK[r * SKS + e] = qkv_w[(size_t)(256 + ch0 + r) * 256 + e];
    }
    for (int i = tid; i < 32 * 132; i += 256) {
        int r = i / 132, j = i % 132;
        sMA[r * SPS + j]  = MN[((size_t)b * 512 + ch0 + r) * 132 + j];
        sNB2[r * SPS + j] = MN[((size_t)b * 512 + 256 + ch0 + r) * 132 + j]
                          + Pk2[(ch0 + r) * 132 + j];
        sPq[r * SPS + j]  = Pq[(ch0 + r) * 132 + j];
        sPk[r * SPS + j]  = Pk[(ch0 + r) * 132 + j];
    }
    __syncthreads();

    const int d = tid & 31, cw = tid >> 5;
    {
        float l0[4] = {0,0,0,0}, dt1[4] = {0,0,0,0}, dt2[4] = {0,0,0,0};
        for (int e = 0; e < 256; e++) {
            float kv = sK[d * SKS + e];
#pragma unroll
            for (int k = 0; k < 4; k++) l0[k] += sU[(8 * k + cw) * SKS + e] * kv;
        }
        for (int j = 0; j < 132; j++) {
            float pk = sPk[d * SPS + j], nb = sNB2[d * SPS + j];
#pragma unroll
            for (int k = 0; k < 4; k++) {
                int c = 8 * k + cw;
                dt1[k] += sMA[c * SPS + j] * pk;
                dt2[k] += sPq[c * SPS + j] * nb;
            }
        }
        float sv = sNB2[d * SPS + 128];
#pragma unroll
        for (int k = 0; k < 4; k++) {
            int c = 8 * k + cw;
            float mm = mod_mult[b * 256 + ch0 + c], mb = mod_bias[b * 256 + ch0 + c];
            sL[c * 33 + d] = mm * (l0[k] + dt1[k] + dt2[k]) + mb * sv;
        }
    }
    __syncthreads();

    {
        int w = tid >> 5, lane = tid & 31;
        const float rs = 0.17677669529663687f;
#pragma unroll
        for (int r = w * 4; r < w * 4 + 4; r++) {
            float v = sL[r * 33 + lane] * rs;
            float mx = v;
#pragma unroll
            for (int o = 16; o; o >>= 1) mx = fmaxf(mx, __shfl_xor_sync(0xffffffffu, mx, o));
            float e = expf(v - mx);
            float s = e;
#pragma unroll
            for (int o = 16; o; o >>= 1) s += __shfl_xor_sync(0xffffffffu, s, o);
            sL[r * 33 + lane] = e / s;
        }
    }
    __syncthreads();

    float* sV = sU;
    for (int i = tid; i < 32 * 64; i += 256) {
        int r = i >> 6, e4 = (i & 63) * 4;
        *(float4*)&sV[r * 256 + e4] =
            *(const float4*)&qkv_w[(size_t)(512 + ch0 + r) * 256 + e4];
    }
    __syncthreads();

    {
        int lane = tid & 31, w = tid >> 5;
        float wrow[32];
#pragma unroll
        for (int dd = 0; dd < 32; dd++) wrow[dd] = sL[lane * 33 + dd];
        for (int i = 0; i < 32; i++) {
            int e = w * 32 + i;
            float acc = 0.f;
#pragma unroll
            for (int dd = 0; dd < 32; dd++) acc += wrow[dd] * sV[dd * 256 + e];
            bf hi = __float2bfloat16(acc);
            bf lo = __float2bfloat16(acc - __bfloat162float(hi));
            size_t idx = ((size_t)b * 256 + ch0 + lane) * 256 + e;
            weh[idx] = hi; wel[idx] = lo;
        }
        if (tid < 32) {
            float acc = 0.f;
            for (int dd = 0; dd < 32; dd++) acc += sL[tid * 33 + dd] * qkv_b[512 + ch0 + dd];
            cb[b * 256 + ch0 + tid] = acc;
        }
    }
}

// ---------------- K9: out_gemm (batch-offset) ----------------
__global__ __launch_bounds__(256, 2)
void out_gemm(const bf* __restrict__ weh, const bf* __restrict__ wel,
              const bf* __restrict__ xh, const bf* __restrict__ xl,
              const float* __restrict__ cb, float* __restrict__ out, int b0) {
    extern __shared__ __align__(16) char dyn[];
    const uint32_t ubase = smem_u32(dyn);
    const int p0 = blockIdx.x * 128;
    const int o0 = blockIdx.y * 128;
    const int b  = blockIdx.z + b0;
    const int tid = threadIdx.x, wid = tid >> 5, lane = tid & 31;
    const int warp_m = (wid & 1) * 64, warp_n = (wid >> 1) * 32;

    float c[4][4][4];
#pragma unroll
    for (int i = 0; i < 4; i++)
#pragma unroll
        for (int j = 0; j < 4; j++)
#pragma unroll
            for (int q = 0; q < 4; q++) c[i][j][q] = 0.f;

    const bf* gAh = weh + ((size_t)b * 256 + o0) * 256;
    const bf* gAl = wel + ((size_t)b * 256 + o0) * 256;
    const bf* gBh = xh + ((size_t)b * HWP + p0) * 256;
    const bf* gBl = xl + ((size_t)b * HWP + p0) * 256;

    mma_pipeline<false>(ubase, 8, gAh, gAl, gBh, gBl, 256, tid, warp_m, warp_n, c);

    const int g = lane >> 2, t = lane & 3;
#pragma unroll
    for (int mt = 0; mt < 4; mt++)
#pragma unroll
        for (int nt = 0; nt < 4; nt++) {
            int p = p0 + warp_n + nt * 8 + 2 * t;
#pragma unroll
            for (int half = 0; half < 2; half++) {
                int o = o0 + warp_m + mt * 16 + g + half * 8;
                float add = cb[b * 256 + o];
                *(float2*)(out + ((size_t)b * 512 + 256 + o) * HWP + p) =
                    make_float2(c[mt][nt][half * 2 + 0] + add,
                                c[mt][nt][half * 2 + 1] + add);
            }
        }
}

// ---------------- launcher ----------------
extern "C" void kernel_launch(void* const* d_in, const int* in_sizes, int n_in,
                              void* d_out, int out_size) {
    const float* x        = (const float*)d_in[0];
    const float* mod_mult = (const float*)d_in[1];
    const float* mod_bias = (const float*)d_in[2];
    const float* qkv_w    = (const float*)d_in[3];
    const float* qkv_b    = (const float*)d_in[4];
    const float* pe_q_h   = (const float*)d_in[5];
    const float* pe_q_w   = (const float*)d_in[6];
    const float* pe_k_h   = (const float*)d_in[7];
    const float* pe_k_w   = (const float*)d_in[8];
    const float* pab      = (const float*)d_in[9];
    const float* pqb      = (const float*)d_in[10];
    float* out = (float*)d_out;

    bf *xh, *xl, *xch, *xcl, *weh, *wel;
    float *XC, *Gp, *U, *MN, *Pq, *Pk, *Pk2, *cb;
    cudaGetSymbolAddress((void**)&xh, g_xh);
    cudaGetSymbolAddress((void**)&xl, g_xl);
    cudaGetSymbolAddress((void**)&xch, g_xch);
    cudaGetSymbolAddress((void**)&xcl, g_xcl);
    cudaGetSymbolAddress((void**)&XC, g_XC);
    cudaGetSymbolAddress((void**)&Gp, g_Gp);
    cudaGetSymbolAddress((void**)&U, g_U);
    cudaGetSymbolAddress((void**)&MN, g_MN);
    cudaGetSymbolAddress((void**)&Pq, g_Pq);
    cudaGetSymbolAddress((void**)&Pk, g_Pk);
    cudaGetSymbolAddress((void**)&Pk2, g_Pk2);
    cudaGetSymbolAddress((void**)&weh, g_weh);
    cudaGetSymbolAddress((void**)&wel, g_wel);
    cudaGetSymbolAddress((void**)&cb, g_cb);

    const int UFSMEM = 256 * GS_STRIDE * 4;   // 69632

    static cudaStream_t s1 = nullptr;
    static cudaEvent_t evStart, evSilu, evMN, evU, evDone;
    if (s1 == nullptr) {
        cudaStreamCreateWithFlags(&s1, cudaStreamNonBlocking);
        cudaEventCreateWithFlags(&evStart, cudaEventDisableTiming);
        cudaEventCreateWithFlags(&evSilu, cudaEventDisableTiming);
        cudaEventCreateWithFlags(&evMN, cudaEventDisableTiming);
        cudaEventCreateWithFlags(&evU, cudaEventDisableTiming);
        cudaEventCreateWithFlags(&evDone, cudaEventDisableTiming);
        cudaFuncSetAttribute(gemmG, cudaFuncAttributeMaxDynamicSharedMemorySize, GSMEM);
        cudaFuncSetAttribute(out_gemm, cudaFuncAttributeMaxDynamicSharedMemorySize, GSMEM);
        cudaFuncSetAttribute(gemmUf, cudaFuncAttributeMaxDynamicSharedMemorySize, UFSMEM);
        cudaFuncSetAttribute(assembly, cudaFuncAttributeMaxDynamicSharedMemorySize, 140000);
    }

    // fork
    cudaEventRecord(evStart, 0);
    cudaStreamWaitEvent(s1, evStart, 0);

    // side: prepP (no deps)
    prepP<<<256, 64, 0, s1>>>(qkv_b, pe_q_h, pe_q_w, pe_k_h, pe_k_w, Pq, Pk, Pk2);

    // main: silu (full)
    silu_split_kernel<<<4096, 256>>>(x, pab, pqb, out, xh, xl, xch, xcl);
    cudaEventRecord(evSilu, 0);

    // side: reduceX -> gemmMAN
    cudaStreamWaitEvent(s1, evSilu, 0);
    reduceX<<<dim3(256, 16), 256, 0, s1>>>(out, pqb, XC);
    gemmMAN<<<dim3(16, 16), 256, 0, s1>>>(qkv_w, XC, MN);
    cudaEventRecord(evMN, s1);

    // main: gemmG (single wave) -> fused reduce+U
    gemmG<<<dim3(3, 6, 16), 256, GSMEM>>>(xch, xcl, Gp);
    gemmUf<<<dim3(4, 16), 256, UFSMEM>>>(qkv_w, Gp, U);
    cudaEventRecord(evU, 0);

    // tail batch-split: A on stream0, B on s1
    cudaStreamWaitEvent(0, evMN, 0);
    assembly<<<dim3(8, 8), 256, 140000>>>(U, qkv_w, qkv_b, MN, Pq, Pk, Pk2,
                                          mod_mult, mod_bias, weh, wel, cb, 0);
    out_gemm<<<dim3(32, 2, 8), 256, GSMEM>>>(weh, wel, xh, xl, cb, out, 0);

    cudaStreamWaitEvent(s1, evU, 0);
    assembly<<<dim3(8, 8), 256, 140000, s1>>>(U, qkv_w, qkv_b, MN, Pq, Pk, Pk2,
                                              mod_mult, mod_bias, weh, wel, cb, 8);
    out_gemm<<<dim3(32, 2, 8), 256, GSMEM, s1>>>(weh, wel, xh, xl, cb, out, 8);
    cudaEventRecord(evDone, s1);

    // join
    cudaStreamWaitEvent(0, evDone, 0);
}

// round 16
// speedup vs baseline: 1.4251x; 1.4251x over previous
#include <cuda_runtime.h>
#include <cuda_bf16.h>
#include <math.h>
#include <stdint.h>

#define B_   16
#define C_   256
#define HWP  4096
#define NH   8

typedef __nv_bfloat16 bf;

// ---------------- scratch ----------------
__device__ bf     g_xh [(size_t)B_ * HWP * C_];
__device__ bf     g_xl [(size_t)B_ * HWP * C_];
__device__ bf     g_xch[(size_t)B_ * C_ * HWP];
__device__ bf     g_xcl[(size_t)B_ * C_ * HWP];
__device__ float  g_XC [(size_t)B_ * C_ * 132];
__device__ float  g_Gp [(size_t)6 * B_ * C_ * C_];
__device__ float  g_G  [(size_t)B_ * C_ * C_];
__device__ float  g_U  [(size_t)B_ * C_ * C_];
__device__ float  g_MN [(size_t)B_ * 512 * 132];
__device__ float  g_Pq [(size_t)C_ * 132];
__device__ float  g_Pk [(size_t)C_ * 132];
__device__ float  g_Pk2[(size_t)C_ * 132];
__device__ bf     g_weh[(size_t)B_ * C_ * C_];
__device__ bf     g_wel[(size_t)B_ * C_ * C_];
__device__ float  g_cb [(size_t)B_ * C_];

// ---------------- helpers ----------------
__device__ __forceinline__ uint32_t smem_u32(const void* p) {
    uint32_t a;
    asm("{ .reg .u64 t; cvta.to.shared.u64 t, %1; cvt.u32.u64 %0, t; }" : "=r"(a) : "l"(p));
    return a;
}
__device__ __forceinline__ void ldsm_x4(uint32_t* r, uint32_t addr) {
    asm volatile("ldmatrix.sync.aligned.m8n8.x4.shared.b16 {%0,%1,%2,%3}, [%4];"
        : "=r"(r[0]), "=r"(r[1]), "=r"(r[2]), "=r"(r[3]) : "r"(addr));
}
__device__ __forceinline__ void mma_bf16(float* c, const uint32_t* a, const uint32_t* b) {
    asm volatile("mma.sync.aligned.m16n8k16.row.col.f32.bf16.bf16.f32 "
        "{%0,%1,%2,%3}, {%4,%5,%6,%7}, {%8,%9}, {%0,%1,%2,%3};"
        : "+f"(c[0]), "+f"(c[1]), "+f"(c[2]), "+f"(c[3])
        : "r"(a[0]), "r"(a[1]), "r"(a[2]), "r"(a[3]), "r"(b[0]), "r"(b[1]));
}
__device__ __forceinline__ float silu_f(float v) { return v / (1.0f + expf(-v)); }

// ---------------- K1: silu -> out[:,0:256]; X splits in 2 layouts ----------------
__global__ __launch_bounds__(256)
void silu_split_kernel(const float* __restrict__ x, const float* __restrict__ pab,
                       const float* __restrict__ pqb, float* __restrict__ out,
                       bf* __restrict__ xh, bf* __restrict__ xl,
                       bf* __restrict__ xch, bf* __restrict__ xcl) {
    __shared__ float s[64][65];
    const int bid = blockIdx.x;
    const int p0 = (bid & 63) * 64;
    const int c0 = ((bid >> 6) & 3) * 64;
    const int b  = bid >> 8;
    const int tid = threadIdx.x;
#pragma unroll
    for (int ii = 0; ii < 4; ii++) {
        int lin = tid + ii * 256;
        int r = lin >> 4, u = lin & 15;
        float4 v = *(const float4*)(x + (size_t)(b * 256 + c0 + r) * HWP + p0 + u * 4);
        float pb = pab[c0 + r];
        float4 o;
        o.x = silu_f(v.x + pb); o.y = silu_f(v.y + pb);
        o.z = silu_f(v.z + pb); o.w = silu_f(v.w + pb);
        __stcs((float4*)(out + (size_t)(b * 512 + c0 + r) * HWP + p0 + u * 4), o);
        float pq = pqb[c0 + r];
        float xp[4] = {o.x + pq, o.y + pq, o.z + pq, o.w + pq};
        s[r][u * 4 + 0] = xp[0]; s[r][u * 4 + 1] = xp[1];
        s[r][u * 4 + 2] = xp[2]; s[r][u * 4 + 3] = xp[3];
        bf h[4], l[4];
#pragma unroll
        for (int j = 0; j < 4; j++) {
            h[j] = __float2bfloat16(xp[j]);
            l[j] = __float2bfloat16(xp[j] - __bfloat162float(h[j]));
        }
        size_t cbase = (size_t)(b * 256 + c0 + r) * HWP + p0 + u * 4;
        __nv_bfloat162 hh0 = {h[0], h[1]}, hh1 = {h[2], h[3]};
        __nv_bfloat162 ll0 = {l[0], l[1]}, ll1 = {l[2], l[3]};
        *(uint2*)(xch + cbase) = make_uint2(*(uint32_t*)&hh0, *(uint32_t*)&hh1);
        *(uint2*)(xcl + cbase) = make_uint2(*(uint32_t*)&ll0, *(uint32_t*)&ll1);
    }
    __syncthreads();
#pragma unroll
    for (int ii = 0; ii < 4; ii++) {
        int lin = tid + ii * 256;
        int r = lin >> 4, u = lin & 15;
        float v[4];
#pragma unroll
        for (int j = 0; j < 4; j++) v[j] = s[u * 4 + j][r];
        bf h[4], l[4];
#pragma unroll
        for (int j = 0; j < 4; j++) {
            h[j] = __float2bfloat16(v[j]);
            l[j] = __float2bfloat16(v[j] - __bfloat162float(h[j]));
        }
        size_t base = (size_t)(b * HWP + p0 + r) * C_ + c0 + u * 4;
        __nv_bfloat162 hh0 = {h[0], h[1]}, hh1 = {h[2], h[3]};
        __nv_bfloat162 ll0 = {l[0], l[1]}, ll1 = {l[2], l[3]};
        __stcs((uint2*)(xh + base), make_uint2(*(uint32_t*)&hh0, *(uint32_t*)&hh1));
        __stcs((uint2*)(xl + base), make_uint2(*(uint32_t*)&ll0, *(uint32_t*)&ll1));
    }
}

// ---------------- K2: reduceX ----------------
__global__ __launch_bounds__(256)
void reduceX(const float* __restrict__ out, const float* __restrict__ pqb,
             float* __restrict__ XC) {
    __shared__ float sm_[64][65];
    __shared__ float rs[64];
    const int e = blockIdx.x, b = blockIdx.y;
    const float4* src = (const float4*)(out + ((size_t)b * 512 + e) * HWP);
    const float pq = pqb[e];
    const int tid = threadIdx.x;
#pragma unroll
    for (int i = 0; i < 4; i++) {
        int idx = tid + i * 256;
        float4 v = src[idx];
        int y = idx >> 4, xc = (idx & 15) * 4;
        sm_[y][xc + 0] = v.x + pq; sm_[y][xc + 1] = v.y + pq;
        sm_[y][xc + 2] = v.z + pq; sm_[y][xc + 3] = v.w + pq;
    }
    __syncthreads();
    float* dst = XC + ((size_t)b * 256 + e) * 132;
    if (tid < 64) {
        float sum = 0.f;
#pragma unroll 8
        for (int xx = 0; xx < 64; xx++) sum += sm_[tid][xx];
        dst[tid] = sum;
        rs[tid] = sum;
    } else if (tid < 128) {
        int xx = tid - 64;
        float sum = 0.f;
#pragma unroll 8
        for (int y = 0; y < 64; y++) sum += sm_[y][xx];
        dst[64 + xx] = sum;
    }
    __syncthreads();
    if (tid == 0) {
        float S = 0.f;
        for (int y = 0; y < 64; y++) S += rs[y];
        dst[128] = S; dst[129] = 0.f; dst[130] = 0.f; dst[131] = 0.f;
    }
}

// ---------------- K3: prepP ----------------
__global__ __launch_bounds__(64)
void prepP(const float* __restrict__ qkv_b,
           const float* __restrict__ peqh, const float* __restrict__ peqw,
           const float* __restrict__ pekh, const float* __restrict__ pekw,
           float* __restrict__ Pq, float* __restrict__ Pk, float* __restrict__ Pk2) {
    const int i = blockIdx.x, t = threadIdx.x;
    __shared__ float red[4];
    float phq = peqh[i * 64 + t], pwq = peqw[i * 64 + t];
    float phk = pekh[i * 64 + t], pwk = pekw[i * 64 + t];
    float kb = qkv_b[256 + i];
    float h = phk, w = pwk;
#pragma unroll
    for (int o = 16; o; o >>= 1) {
        h += __shfl_xor_sync(0xffffffffu, h, o);
        w += __shfl_xor_sync(0xffffffffu, w, o);
    }
    if ((t & 31) == 0) { red[(t >> 5) * 2] = h; red[(t >> 5) * 2 + 1] = w; }
    __syncthreads();
    float Hks = red[0] + red[2], Wks = red[1] + red[3];
    Pq[i * 132 + t] = phq;       Pq[i * 132 + 64 + t] = pwq;
    Pk[i * 132 + t] = phk;       Pk[i * 132 + 64 + t] = pwk;
    Pk2[i * 132 + t]      = 64.f * kb + 64.f * phk + Wks;
    Pk2[i * 132 + 64 + t] = 64.f * kb + 64.f * pwk + Hks;
    if (t == 0) {
        Pq[i * 132 + 128] = qkv_b[i];
        Pk[i * 132 + 128] = kb;
        Pk2[i * 132 + 128] = 4096.f * kb + 64.f * Hks + 64.f * Wks;
        for (int j = 129; j < 132; j++) { Pq[i*132+j] = 0.f; Pk[i*132+j] = 0.f; Pk2[i*132+j] = 0.f; }
    }
}

// ---------------- mma split pipeline ----------------
#define KC        32
#define TILE_BYT  8192
#define GSMEM     (3 * 4 * TILE_BYT)

__device__ __forceinline__ void load_tile_sw(uint32_t sm, const bf* g, size_t ld, int tid) {
#pragma unroll
    for (int ii = 0; ii < 2; ii++) {
        int lin = tid + ii * 256;
        int r = lin >> 2, u = lin & 3;
        uint32_t dst = sm + r * 64 + ((u ^ ((r >> 1) & 3)) * 16);
        const bf* src = g + (size_t)r * ld + u * 8;
        asm volatile("cp.async.cg.shared.global [%0], [%1], 16;" :: "r"(dst), "l"(src));
    }
}

template <bool DIAG>
__device__ __forceinline__ void issue_stage(uint32_t sbase,
    const bf* gAh, const bf* gAl, const bf* gBh, const bf* gBl,
    size_t ld, int ch, int tid) {
    load_tile_sw(sbase + 0 * TILE_BYT, gAh + (size_t)ch * KC, ld, tid);
    load_tile_sw(sbase + 1 * TILE_BYT, gAl + (size_t)ch * KC, ld, tid);
    if (!DIAG) {
        load_tile_sw(sbase + 2 * TILE_BYT, gBh + (size_t)ch * KC, ld, tid);
        load_tile_sw(sbase + 3 * TILE_BYT, gBl + (size_t)ch * KC, ld, tid);
    }
    asm volatile("cp.async.commit_group;");
}

template <bool DIAG>
__device__ __forceinline__ void mma_pipeline(uint32_t ubase, int nch,
    const bf* gAh, const bf* gAl, const bf* gBh, const bf* gBl, size_t ld,
    int tid, int warp_m, int warp_n, float c[4][4][4]) {
    const uint32_t STG = (DIAG ? 2 : 4) * TILE_BYT;
    const int lane = tid & 31;
    uint32_t a_off[2], b_off[2];
    {
        const int sw  = (lane >> 1) & 3;
        const int l15 = lane & 15;
        const int rit = ((lane >> 4) << 3) + (lane & 7);
#pragma unroll
        for (int ks = 0; ks < 2; ks++) {
            a_off[ks] = (uint32_t)l15 * 64 + (uint32_t)(((ks * 2 + (lane >> 4)) ^ sw) * 16);
            b_off[ks] = (uint32_t)rit * 64 + (uint32_t)(((ks * 2 + ((lane >> 3) & 1)) ^ sw) * 16);
        }
    }

    issue_stage<DIAG>(ubase + 0 * STG, gAh, gAl, gBh, gBl, ld, 0, tid);
    issue_stage<DIAG>(ubase + 1 * STG, gAh, gAl, gBh, gBl, ld, 1, tid);

    int st = 0;
    for (int ch = 0; ch < nch; ch++) {
        if (ch < nch - 1) { asm volatile("cp.async.wait_group 1;"); }
        else              { asm volatile("cp.async.wait_group 0;"); }
        __syncthreads();
        if (ch + 2 < nch) {
            int st2 = st + 2; if (st2 >= 3) st2 -= 3;
            issue_stage<DIAG>(ubase + (uint32_t)st2 * STG,
                              gAh, gAl, gBh, gBl, ld, ch + 2, tid);
        }

        const uint32_t uAh = ubase + (uint32_t)st * STG;
        const uint32_t uAl = uAh + TILE_BYT;
        const uint32_t uBh = DIAG ? uAh : (uAh + 2 * TILE_BYT);
        const uint32_t uBl = DIAG ? uAl : (uAh + 3 * TILE_BYT);
#pragma unroll
        for (int ks = 0; ks < 2; ks++) {
            uint32_t ah[4][4], al[4][4], bh[4][2], bl[4][2];
#pragma unroll
            for (int mt = 0; mt < 4; mt++) {
                uint32_t ra = (uint32_t)(warp_m + mt * 16) * 64;
                ldsm_x4(ah[mt], uAh + ra + a_off[ks]);
                ldsm_x4(al[mt], uAl + ra + a_off[ks]);
            }
#pragma unroll
            for (int nt2 = 0; nt2 < 2; nt2++) {
                uint32_t rb = (uint32_t)(warp_n + nt2 * 16) * 64;
                uint32_t t0[4], t1[4];
                ldsm_x4(t0, uBh + rb + b_off[ks]);
                ldsm_x4(t1, uBl + rb + b_off[ks]);
                bh[nt2 * 2][0] = t0[0]; bh[nt2 * 2][1] = t0[1];
                bh[nt2 * 2 + 1][0] = t0[2]; bh[nt2 * 2 + 1][1] = t0[3];
                bl[nt2 * 2][0] = t1[0]; bl[nt2 * 2][1] = t1[1];
                bl[nt2 * 2 + 1][0] = t1[2]; bl[nt2 * 2 + 1][1] = t1[3];
            }
#pragma unroll
            for (int mt = 0; mt < 4; mt++)
#pragma unroll
                for (int nt = 0; nt < 4; nt++) mma_bf16(c[mt][nt], ah[mt], bh[nt]);
#pragma unroll
            for (int mt = 0; mt < 4; mt++)
#pragma unroll
                for (int nt = 0; nt < 4; nt++) mma_bf16(c[mt][nt], ah[mt], bl[nt]);
#pragma unroll
            for (int mt = 0; mt < 4; mt++)
#pragma unroll
                for (int nt = 0; nt < 4; nt++) mma_bf16(c[mt][nt], al[mt], bh[nt]);
        }
        if (++st == 3) st = 0;
    }
    __syncthreads();
}

// ---------------- K4: G partials ----------------
__global__ __launch_bounds__(256, 2)
void gemmG(const bf* __restrict__ xch, const bf* __restrict__ xcl,
           float* __restrict__ Gp) {
    extern __shared__ __align__(16) char dyn[];
    const uint32_t ubase = smem_u32(dyn);
    const int tile = blockIdx.x;
    const int e0 = (tile == 2) ? 128 : 0;
    const int f0 = (tile == 0) ? 0 : 128;
    const bool diag = (tile != 1);
    const int s = blockIdx.y;
    const int b = blockIdx.z;
    const int start = 21 * s + (s > 4 ? s - 4 : 0);
    const int nch   = (s < 4) ? 21 : 22;
    const int tid = threadIdx.x, wid = tid >> 5, lane = tid & 31;
    const int warp_m = (wid & 1) * 64, warp_n = (wid >> 1) * 32;

    float c[4][4][4];
#pragma unroll
    for (int i = 0; i < 4; i++)
#pragma unroll
        for (int j = 0; j < 4; j++)
#pragma unroll
            for (int q = 0; q < 4; q++) c[i][j][q] = 0.f;

    const size_t noff = (size_t)start * KC;
    const bf* gAh = xch + ((size_t)b * 256 + e0) * HWP + noff;
    const bf* gAl = xcl + ((size_t)b * 256 + e0) * HWP + noff;
    const bf* gBh = xch + ((size_t)b * 256 + f0) * HWP + noff;
    const bf* gBl = xcl + ((size_t)b * 256 + f0) * HWP + noff;

    if (diag)
        mma_pipeline<true>(ubase, nch, gAh, gAl, gBh, gBl, HWP, tid, warp_m, warp_n, c);
    else
        mma_pipeline<false>(ubase, nch, gAh, gAl, gBh, gBl, HWP, tid, warp_m, warp_n, c);

    const int g = lane >> 2, t = lane & 3;
    float* dst = Gp + (size_t)(b * 6 + s) * 65536;
#pragma unroll
    for (int mt = 0; mt < 4; mt++)
#pragma unroll
        for (int nt = 0; nt < 4; nt++) {
            int f = f0 + warp_n + nt * 8 + 2 * t;
#pragma unroll
            for (int half = 0; half < 2; half++) {
                int e = e0 + warp_m + mt * 16 + g + half * 8;
                *(float2*)&dst[(size_t)e * 256 + f] =
                    make_float2(c[mt][nt][half * 2 + 0], c[mt][nt][half * 2 + 1]);
            }
        }
}

// ---------------- K5: reduceG ----------------
__global__ __launch_bounds__(256)
void reduceG(const float* __restrict__ Gp, float* __restrict__ G) {
    __shared__ float tile[64][65];
    const int bt = blockIdx.x;
    const int b  = blockIdx.y;
    const int eT = bt >> 2, fT = bt & 3;
    const int e0 = eT * 64, f0 = fT * 64;
    const bool mirror = (e0 >= 128) && (f0 < 128);
    const int tid = threadIdx.x;
    float4 acc[4];
    int rr[4], cc4[4];
#pragma unroll
    for (int i = 0; i < 4; i++) {
        int lin = tid + i * 256;
        rr[i] = lin >> 4; cc4[i] = (lin & 15) * 4;
        acc[i] = make_float4(0.f, 0.f, 0.f, 0.f);
    }
#pragma unroll
    for (int z = 0; z < 6; z++) {
        const float* s = Gp + ((size_t)(b * 6 + z)) * 65536;
#pragma unroll
        for (int i = 0; i < 4; i++) {
            int sr = mirror ? (f0 + rr[i]) : (e0 + rr[i]);
            int sc = mirror ? (e0 + cc4[i]) : (f0 + cc4[i]);
            float4 v = *(const float4*)&s[(size_t)sr * 256 + sc];
            acc[i].x += v.x; acc[i].y += v.y; acc[i].z += v.z; acc[i].w += v.w;
        }
    }
    float* dst = G + (size_t)b * 65536;
    if (!mirror) {
#pragma unroll
        for (int i = 0; i < 4; i++)
            *(float4*)&dst[(size_t)(e0 + rr[i]) * 256 + f0 + cc4[i]] = acc[i];
    } else {
#pragma unroll
        for (int i = 0; i < 4; i++) {
            tile[rr[i]][cc4[i] + 0] = acc[i].x;
            tile[rr[i]][cc4[i] + 1] = acc[i].y;
            tile[rr[i]][cc4[i] + 2] = acc[i].z;
            tile[rr[i]][cc4[i] + 3] = acc[i].w;
        }
        __syncthreads();
#pragma unroll
        for (int i = 0; i < 4; i++) {
            int r = rr[i], c4 = cc4[i];
            float4 o = make_float4(tile[c4 + 0][r], tile[c4 + 1][r],
                                   tile[c4 + 2][r], tile[c4 + 3][r]);
            *(float4*)&dst[(size_t)(e0 + r) * 256 + f0 + c4] = o;
        }
    }
}

// ---------------- K6: gemmU ----------------
__global__ __launch_bounds__(256)
void gemmU(const float* __restrict__ Wq, const float* __restrict__ G,
           float* __restrict__ U) {
    __shared__ float As[16][68];
    __shared__ float Bs[16][68];
    const int i0 = blockIdx.x * 64, j0 = blockIdx.y * 64, b = blockIdx.z;
    const int tid = threadIdx.x, ty = tid >> 4, tx = tid & 15;
    const float* Gb = G + (size_t)b * 65536;
    float acc[4][4] = {};
    for (int k0 = 0; k0 < 256; k0 += 16) {
        {
            int i = tid >> 2, k4 = (tid & 3) * 4;
            float4 a = *(const float4*)&Wq[(size_t)(i0 + i) * 256 + k0 + k4];
            As[k4 + 0][i] = a.x; As[k4 + 1][i] = a.y;
            As[k4 + 2][i] = a.z; As[k4 + 3][i] = a.w;
            int k = tid >> 4, j4 = (tid & 15) * 4;
            *(float4*)&Bs[k][j4] = *(const float4*)&Gb[(size_t)(k0 + k) * 256 + j0 + j4];
        }
        __syncthreads();
#pragma unroll
        for (int k = 0; k < 16; k++) {
            float a[4], bb[4];
#pragma unroll
            for (int x = 0; x < 4; x++) a[x] = As[k][ty * 4 + x];
#pragma unroll
            for (int x = 0; x < 4; x++) bb[x] = Bs[k][tx * 4 + x];
#pragma unroll
            for (int ii = 0; ii < 4; ii++)
#pragma unroll
                for (int jj = 0; jj < 4; jj++) acc[ii][jj] += a[ii] * bb[jj];
        }
        __syncthreads();
    }
#pragma unroll
    for (int ii = 0; ii < 4; ii++)
        *(float4*)&U[((size_t)b * 256 + i0 + ty * 4 + ii) * 256 + j0 + tx * 4] =
            make_float4(acc[ii][0], acc[ii][1], acc[ii][2], acc[ii][3]);
}

// ---------------- K7: gemmMAN ----------------
__global__ __launch_bounds__(256)
void gemmMAN(const float* __restrict__ qkv_w, const float* __restrict__ XC,
             float* __restrict__ MN) {
    __shared__ float Ws[32][36];
    __shared__ float XCs[32][132];
    const int r0 = blockIdx.x * 32;
    const int b  = blockIdx.y;
    const int tid = threadIdx.x;
    const int w   = tid >> 5;
    const int lane = tid & 31;
    float acc[4][5];
#pragma unroll
    for (int i = 0; i < 4; i++)
#pragma unroll
        for (int cg = 0; cg < 5; cg++) acc[i][cg] = 0.f;
    const bool has5 = (lane < 4);

    for (int k0 = 0; k0 < 256; k0 += 32) {
        {
            int r = tid >> 3, k4 = (tid & 7) * 4;
            *(float4*)&Ws[r][k4] = *(const float4*)&qkv_w[(size_t)(r0 + r) * 256 + k0 + k4];
        }
#pragma unroll
        for (int it = 0; it < 5; it++) {
            int f4 = tid + it * 256;
            if (f4 < 1056) {
                int k = f4 / 33, g = f4 % 33;
                *(float4*)&XCs[k][g * 4] =
                    *(const float4*)&XC[((size_t)b * 256 + k0 + k) * 132 + g * 4];
            }
        }
        __syncthreads();
#pragma unroll 4
        for (int k = 0; k < 32; k++) {
            float xv[5];
#pragma unroll
            for (int cg = 0; cg < 4; cg++) xv[cg] = XCs[k][lane + 32 * cg];
            xv[4] = has5 ? XCs[k][lane + 128] : 0.f;
#pragma unroll
            for (int i = 0; i < 4; i++) {
                float wv = Ws[w * 4 + i][k];
#pragma unroll
                for (int cg = 0; cg < 5; cg++) acc[i][cg] += wv * xv[cg];
            }
        }
        __syncthreads();
    }
#pragma unroll
    for (int i = 0; i < 4; i++) {
        float* dst = MN + ((size_t)b * 512 + r0 + w * 4 + i) * 132;
#pragma unroll
        for (int cg = 0; cg < 4; cg++) dst[lane + 32 * cg] = acc[i][cg];
        if (has5) dst[lane + 128] = acc[i][4];
    }
}

// ---------------- K8: assembly ----------------
#define SKS 257
#define SPS 133
__global__ __launch_bounds__(256)
void assembly(const float* __restrict__ U, const float* __restrict__ qkv_w,
              const float* __restrict__ qkv_b, const float* __restrict__ MN,
              const float* __restrict__ Pq, const float* __restrict__ Pk,
              const float* __restrict__ Pk2,
              const float* __restrict__ mod_mult, const float* __restrict__ mod_bias,
              bf* __restrict__ weh, bf* __restrict__ wel, float* __restrict__ cb) {
    extern __shared__ float sm[];
    float* sU  = sm;
    float* sK  = sU + 32 * SKS;
    float* sMA = sK + 32 * SKS;
    float* sPq = sMA + 32 * SPS;
    float* sPk = sPq + 32 * SPS;
    float* sNB2 = sPk + 32 * SPS;
    float* sL  = sNB2 + 32 * SPS;
    const int h = blockIdx.x, b = blockIdx.y;
    const int ch0 = h * 32;
    const int tid = threadIdx.x;

    for (int i = tid; i < 32 * 256; i += 256) {
        int r = i >> 8, e = i & 255;
        sU[r * SKS + e] = U[((size_t)b * 256 + ch0 + r) * 256 + e];
        sK[r * SKS + e] = qkv_w[(size_t)(256 + ch0 + r) * 256 + e];
    }
    for (int i = tid; i < 32 * 132; i += 256) {
        int r = i / 132, j = i % 132;
        sMA[r * SPS + j]  = MN[((size_t)b * 512 + ch0 + r) * 132 + j];
        sNB2[r * SPS + j] = MN[((size_t)b * 512 + 256 + ch0 + r) * 132 + j]
                          + Pk2[(ch0 + r) * 132 + j];
        sPq[r * SPS + j]  = Pq[(ch0 + r) * 132 + j];
        sPk[r * SPS + j]  = Pk[(ch0 + r) * 132 + j];
    }
    __syncthreads();

    const int d = tid & 31, cw = tid >> 5;
    {
        float l0[4] = {0,0,0,0}, dt1[4] = {0,0,0,0}, dt2[4] = {0,0,0,0};
        for (int e = 0; e < 256; e++) {
            float kv = sK[d * SKS + e];
#pragma unroll
            for (int k = 0; k < 4; k++) l0[k] += sU[(8 * k + cw) * SKS + e] * kv;
        }
        for (int j = 0; j < 132; j++) {
            float pk = sPk[d * SPS + j], nb = sNB2[d * SPS + j];
#pragma unroll
            for (int k = 0; k < 4; k++) {
                int c = 8 * k + cw;
                dt1[k] += sMA[c * SPS + j] * pk;
                dt2[k] += sPq[c * SPS + j] * nb;
            }
        }
        float sv = sNB2[d * SPS + 128];
#pragma unroll
        for (int k = 0; k < 4; k++) {
            int c = 8 * k + cw;
            float mm = mod_mult[b * 256 + ch0 + c], mb = mod_bias[b * 256 + ch0 + c];
            sL[c * 33 + d] = mm * (l0[k] + dt1[k] + dt2[k]) + mb * sv;
        }
    }
    __syncthreads();

    {
        int w = tid >> 5, lane = tid & 31;
        const float rs = 0.17677669529663687f;
#pragma unroll
        for (int r = w * 4; r < w * 4 + 4; r++) {
            float v = sL[r * 33 + lane] * rs;
            float mx = v;
#pragma unroll
            for (int o = 16; o; o >>= 1) mx = fmaxf(mx, __shfl_xor_sync(0xffffffffu, mx, o));
            float e = expf(v - mx);
            float s = e;
#pragma unroll
            for (int o = 16; o; o >>= 1) s += __shfl_xor_sync(0xffffffffu, s, o);
            sL[r * 33 + lane] = e / s;
        }
    }
    __syncthreads();

    float* sV = sU;
    for (int i = tid; i < 32 * 64; i += 256) {
        int r = i >> 6, e4 = (i & 63) * 4;
        *(float4*)&sV[r * 256 + e4] =
            *(const float4*)&qkv_w[(size_t)(512 + ch0 + r) * 256 + e4];
    }
    __syncthreads();

    {
        int lane = tid & 31, w = tid >> 5;
        float wrow[32];
#pragma unroll
        for (int dd = 0; dd < 32; dd++) wrow[dd] = sL[lane * 33 + dd];
        for (int i = 0; i < 32; i++) {
            int e = w * 32 + i;
            float acc = 0.f;
#pragma unroll
            for (int dd = 0; dd < 32; dd++) acc += wrow[dd] * sV[dd * 256 + e];
            bf hi = __float2bfloat16(acc);
            bf lo = __float2bfloat16(acc - __bfloat162float(hi));
            size_t idx = ((size_t)b * 256 + ch0 + lane) * 256 + e;
            weh[idx] = hi; wel[idx] = lo;
        }
        if (tid < 32) {
            float acc = 0.f;
            for (int dd = 0; dd < 32; dd++) acc += sL[tid * 33 + dd] * qkv_b[512 + ch0 + dd];
            cb[b * 256 + ch0 + tid] = acc;
        }
    }
}

// ---------------- K9: out_gemm ----------------
__global__ __launch_bounds__(256, 2)
void out_gemm(const bf* __restrict__ weh, const bf* __restrict__ wel,
              const bf* __restrict__ xh, const bf* __restrict__ xl,
              const float* __restrict__ cb, float* __restrict__ out) {
    extern __shared__ __align__(16) char dyn[];
    const uint32_t ubase = smem_u32(dyn);
    const int p0 = blockIdx.x * 128;
    const int o0 = blockIdx.y * 128;
    const int b  = blockIdx.z;
    const int tid = threadIdx.x, wid = tid >> 5, lane = tid & 31;
    const int warp_m = (wid & 1) * 64, warp_n = (wid >> 1) * 32;

    float c[4][4][4];
#pragma unroll
    for (int i = 0; i < 4; i++)
#pragma unroll
        for (int j = 0; j < 4; j++)
#pragma unroll
            for (int q = 0; q < 4; q++) c[i][j][q] = 0.f;

    const bf* gAh = weh + ((size_t)b * 256 + o0) * 256;
    const bf* gAl = wel + ((size_t)b * 256 + o0) * 256;
    const bf* gBh = xh + ((size_t)b * HWP + p0) * 256;
    const bf* gBl = xl + ((size_t)b * HWP + p0) * 256;

    mma_pipeline<false>(ubase, 8, gAh, gAl, gBh, gBl, 256, tid, warp_m, warp_n, c);

    const int g = lane >> 2, t = lane & 3;
#pragma unroll
    for (int mt = 0; mt < 4; mt++)
#pragma unroll
        for (int nt = 0; nt < 4; nt++) {
            int p = p0 + warp_n + nt * 8 + 2 * t;
#pragma unroll
            for (int half = 0; half < 2; half++) {
                int o = o0 + warp_m + mt * 16 + g + half * 8;
                float add = cb[b * 256 + o];
                *(float2*)(out + ((size_t)b * 512 + 256 + o) * HWP + p) =
                    make_float2(c[mt][nt][half * 2 + 0] + add,
                                c[mt][nt][half * 2 + 1] + add);
            }
        }
}

// ---------------- launcher (round-13 two-stream DAG) ----------------
extern "C" void kernel_launch(void* const* d_in, const int* in_sizes, int n_in,
                              void* d_out, int out_size) {
    const float* x        = (const float*)d_in[0];
    const float* mod_mult = (const float*)d_in[1];
    const float* mod_bias = (const float*)d_in[2];
    const float* qkv_w    = (const float*)d_in[3];
    const float* qkv_b    = (const float*)d_in[4];
    const float* pe_q_h   = (const float*)d_in[5];
    const float* pe_q_w   = (const float*)d_in[6];
    const float* pe_k_h   = (const float*)d_in[7];
    const float* pe_k_w   = (const float*)d_in[8];
    const float* pab      = (const float*)d_in[9];
    const float* pqb      = (const float*)d_in[10];
    float* out = (float*)d_out;

    bf *xh, *xl, *xch, *xcl, *weh, *wel;
    float *XC, *Gp, *G, *U, *MN, *Pq, *Pk, *Pk2, *cb;
    cudaGetSymbolAddress((void**)&xh, g_xh);
    cudaGetSymbolAddress((void**)&xl, g_xl);
    cudaGetSymbolAddress((void**)&xch, g_xch);
    cudaGetSymbolAddress((void**)&xcl, g_xcl);
    cudaGetSymbolAddress((void**)&XC, g_XC);
    cudaGetSymbolAddress((void**)&Gp, g_Gp);
    cudaGetSymbolAddress((void**)&G, g_G);
    cudaGetSymbolAddress((void**)&U, g_U);
    cudaGetSymbolAddress((void**)&MN, g_MN);
    cudaGetSymbolAddress((void**)&Pq, g_Pq);
    cudaGetSymbolAddress((void**)&Pk, g_Pk);
    cudaGetSymbolAddress((void**)&Pk2, g_Pk2);
    cudaGetSymbolAddress((void**)&weh, g_weh);
    cudaGetSymbolAddress((void**)&wel, g_wel);
    cudaGetSymbolAddress((void**)&cb, g_cb);

    static cudaStream_t s1 = nullptr;
    static cudaEvent_t evStart = nullptr, evSilu = nullptr, evSide = nullptr;
    if (s1 == nullptr) {
        cudaStreamCreateWithFlags(&s1, cudaStreamNonBlocking);
        cudaEventCreateWithFlags(&evStart, cudaEventDisableTiming);
        cudaEventCreateWithFlags(&evSilu, cudaEventDisableTiming);
        cudaEventCreateWithFlags(&evSide, cudaEventDisableTiming);
        cudaFuncSetAttribute(gemmG, cudaFuncAttributeMaxDynamicSharedMemorySize, GSMEM);
        cudaFuncSetAttribute(out_gemm, cudaFuncAttributeMaxDynamicSharedMemorySize, GSMEM);
        cudaFuncSetAttribute(assembly, cudaFuncAttributeMaxDynamicSharedMemorySize, 140000);
    }

    // fork: side stream starts with prepP (no deps)
    cudaEventRecord(evStart, 0);
    cudaStreamWaitEvent(s1, evStart, 0);
    prepP<<<256, 64, 0, s1>>>(qkv_b, pe_q_h, pe_q_w, pe_k_h, pe_k_w, Pq, Pk, Pk2);

    // main: silu
    silu_split_kernel<<<4096, 256>>>(x, pab, pqb, out, xh, xl, xch, xcl);
    cudaEventRecord(evSilu, 0);

    // side: reduceX -> gemmMAN
    cudaStreamWaitEvent(s1, evSilu, 0);
    reduceX<<<dim3(256, 16), 256, 0, s1>>>(out, pqb, XC);
    gemmMAN<<<dim3(16, 16), 256, 0, s1>>>(qkv_w, XC, MN);
    cudaEventRecord(evSide, s1);

    // main: gemmG -> reduceG -> gemmU
    gemmG<<<dim3(3, 6, 16), 256, GSMEM>>>(xch, xcl, Gp);
    reduceG<<<dim3(16, 16), 256>>>(Gp, G);
    gemmU<<<dim3(4, 4, 16), 256>>>(qkv_w, G, U);

    // join: assembly needs MN (side) + U (main)
    cudaStreamWaitEvent(0, evSide, 0);
    assembly<<<dim3(8, 16), 256, 140000>>>(U, qkv_w, qkv_b, MN, Pq, Pk, Pk2,
                                           mod_mult, mod_bias, weh, wel, cb);
    out_gemm<<<dim3(32, 2, 16), 256, GSMEM>>>(weh, wel, xh, xl, cb, out);
}

// round 17
// speedup vs baseline: 1.4984x; 1.0514x over previous
#include <cuda_runtime.h>
#include <cuda_bf16.h>
#include <math.h>
#include <stdint.h>

#define B_   16
#define C_   256
#define HWP  4096
#define NH   8

typedef __nv_bfloat16 bf;

// ---------------- scratch ----------------
__device__ bf     g_xch[(size_t)B_ * C_ * HWP];     // X hi [b][e][n]
__device__ bf     g_xcl[(size_t)B_ * C_ * HWP];     // X lo [b][e][n]
__device__ float  g_XC [(size_t)B_ * C_ * 132];
__device__ float  g_Gp [(size_t)6 * B_ * C_ * C_];
__device__ float  g_G  [(size_t)B_ * C_ * C_];
__device__ float  g_U  [(size_t)B_ * C_ * C_];
__device__ float  g_MN [(size_t)B_ * 512 * 132];
__device__ float  g_Pq [(size_t)C_ * 132];
__device__ float  g_Pk [(size_t)C_ * 132];
__device__ float  g_Pk2[(size_t)C_ * 132];
__device__ bf     g_weh[(size_t)B_ * C_ * C_];
__device__ bf     g_wel[(size_t)B_ * C_ * C_];
__device__ float  g_cb [(size_t)B_ * C_];

// ---------------- helpers ----------------
__device__ __forceinline__ uint32_t smem_u32(const void* p) {
    uint32_t a;
    asm("{ .reg .u64 t; cvta.to.shared.u64 t, %1; cvt.u32.u64 %0, t; }" : "=r"(a) : "l"(p));
    return a;
}
__device__ __forceinline__ void ldsm_x4(uint32_t* r, uint32_t addr) {
    asm volatile("ldmatrix.sync.aligned.m8n8.x4.shared.b16 {%0,%1,%2,%3}, [%4];"
        : "=r"(r[0]), "=r"(r[1]), "=r"(r[2]), "=r"(r[3]) : "r"(addr));
}
__device__ __forceinline__ void ldsm_x4_tr(uint32_t* r, uint32_t addr) {
    asm volatile("ldmatrix.sync.aligned.m8n8.x4.trans.shared.b16 {%0,%1,%2,%3}, [%4];"
        : "=r"(r[0]), "=r"(r[1]), "=r"(r[2]), "=r"(r[3]) : "r"(addr));
}
__device__ __forceinline__ void mma_bf16(float* c, const uint32_t* a, const uint32_t* b) {
    asm volatile("mma.sync.aligned.m16n8k16.row.col.f32.bf16.bf16.f32 "
        "{%0,%1,%2,%3}, {%4,%5,%6,%7}, {%8,%9}, {%0,%1,%2,%3};"
        : "+f"(c[0]), "+f"(c[1]), "+f"(c[2]), "+f"(c[3])
        : "r"(a[0]), "r"(a[1]), "r"(a[2]), "r"(a[3]), "r"(b[0]), "r"(b[1]));
}
__device__ __forceinline__ float silu_f(float v) { return v / (1.0f + __expf(-v)); }

// ---------------- K1: silu (single pass, no smem) ----------------
__global__ __launch_bounds__(256)
void silu_split_kernel(const float* __restrict__ x, const float* __restrict__ pab,
                       const float* __restrict__ pqb, float* __restrict__ out,
                       bf* __restrict__ xch, bf* __restrict__ xcl) {
    const int bid = blockIdx.x;
    const int p0 = (bid & 63) * 64;
    const int c0 = ((bid >> 6) & 3) * 64;
    const int b  = bid >> 8;
    const int tid = threadIdx.x;
#pragma unroll
    for (int ii = 0; ii < 4; ii++) {
        int lin = tid + ii * 256;
        int r = lin >> 4, u = lin & 15;
        float4 v = *(const float4*)(x + (size_t)(b * 256 + c0 + r) * HWP + p0 + u * 4);
        float pb = pab[c0 + r];
        float4 o;
        o.x = silu_f(v.x + pb); o.y = silu_f(v.y + pb);
        o.z = silu_f(v.z + pb); o.w = silu_f(v.w + pb);
        *(float4*)(out + (size_t)(b * 512 + c0 + r) * HWP + p0 + u * 4) = o;
        float pq = pqb[c0 + r];
        float xp[4] = {o.x + pq, o.y + pq, o.z + pq, o.w + pq};
        bf h[4], l[4];
#pragma unroll
        for (int j = 0; j < 4; j++) {
            h[j] = __float2bfloat16(xp[j]);
            l[j] = __float2bfloat16(xp[j] - __bfloat162float(h[j]));
        }
        size_t cbase = (size_t)(b * 256 + c0 + r) * HWP + p0 + u * 4;
        __nv_bfloat162 hh0 = {h[0], h[1]}, hh1 = {h[2], h[3]};
        __nv_bfloat162 ll0 = {l[0], l[1]}, ll1 = {l[2], l[3]};
        *(uint2*)(xch + cbase) = make_uint2(*(uint32_t*)&hh0, *(uint32_t*)&hh1);
        *(uint2*)(xcl + cbase) = make_uint2(*(uint32_t*)&ll0, *(uint32_t*)&ll1);
    }
}

// ---------------- K2: reduceX ----------------
__global__ __launch_bounds__(256)
void reduceX(const float* __restrict__ out, const float* __restrict__ pqb,
             float* __restrict__ XC) {
    __shared__ float sm_[64][65];
    __shared__ float rs[64];
    const int e = blockIdx.x, b = blockIdx.y;
    const float4* src = (const float4*)(out + ((size_t)b * 512 + e) * HWP);
    const float pq = pqb[e];
    const int tid = threadIdx.x;
#pragma unroll
    for (int i = 0; i < 4; i++) {
        int idx = tid + i * 256;
        float4 v = src[idx];
        int y = idx >> 4, xc = (idx & 15) * 4;
        sm_[y][xc + 0] = v.x + pq; sm_[y][xc + 1] = v.y + pq;
        sm_[y][xc + 2] = v.z + pq; sm_[y][xc + 3] = v.w + pq;
    }
    __syncthreads();
    float* dst = XC + ((size_t)b * 256 + e) * 132;
    if (tid < 64) {
        float sum = 0.f;
#pragma unroll 8
        for (int xx = 0; xx < 64; xx++) sum += sm_[tid][xx];
        dst[tid] = sum;
        rs[tid] = sum;
    } else if (tid < 128) {
        int xx = tid - 64;
        float sum = 0.f;
#pragma unroll 8
        for (int y = 0; y < 64; y++) sum += sm_[y][xx];
        dst[64 + xx] = sum;
    }
    __syncthreads();
    if (tid == 0) {
        float S = 0.f;
        for (int y = 0; y < 64; y++) S += rs[y];
        dst[128] = S; dst[129] = 0.f; dst[130] = 0.f; dst[131] = 0.f;
    }
}

// ---------------- K3: prepP ----------------
__global__ __launch_bounds__(64)
void prepP(const float* __restrict__ qkv_b,
           const float* __restrict__ peqh, const float* __restrict__ peqw,
           const float* __restrict__ pekh, const float* __restrict__ pekw,
           float* __restrict__ Pq, float* __restrict__ Pk, float* __restrict__ Pk2) {
    const int i = blockIdx.x, t = threadIdx.x;
    __shared__ float red[4];
    float phq = peqh[i * 64 + t], pwq = peqw[i * 64 + t];
    float phk = pekh[i * 64 + t], pwk = pekw[i * 64 + t];
    float kb = qkv_b[256 + i];
    float h = phk, w = pwk;
#pragma unroll
    for (int o = 16; o; o >>= 1) {
        h += __shfl_xor_sync(0xffffffffu, h, o);
        w += __shfl_xor_sync(0xffffffffu, w, o);
    }
    if ((t & 31) == 0) { red[(t >> 5) * 2] = h; red[(t >> 5) * 2 + 1] = w; }
    __syncthreads();
    float Hks = red[0] + red[2], Wks = red[1] + red[3];
    Pq[i * 132 + t] = phq;       Pq[i * 132 + 64 + t] = pwq;
    Pk[i * 132 + t] = phk;       Pk[i * 132 + 64 + t] = pwk;
    Pk2[i * 132 + t]      = 64.f * kb + 64.f * phk + Wks;
    Pk2[i * 132 + 64 + t] = 64.f * kb + 64.f * pwk + Hks;
    if (t == 0) {
        Pq[i * 132 + 128] = qkv_b[i];
        Pk[i * 132 + 128] = kb;
        Pk2[i * 132 + 128] = 4096.f * kb + 64.f * Hks + 64.f * Wks;
        for (int j = 129; j < 132; j++) { Pq[i*132+j] = 0.f; Pk[i*132+j] = 0.f; Pk2[i*132+j] = 0.f; }
    }
}

// ---------------- mma split pipeline (gemmG, unchanged) ----------------
#define KC        32
#define TILE_BYT  8192
#define GSMEM     (3 * 4 * TILE_BYT)

__device__ __forceinline__ void load_tile_sw(uint32_t sm, const bf* g, size_t ld, int tid) {
#pragma unroll
    for (int ii = 0; ii < 2; ii++) {
        int lin = tid + ii * 256;
        int r = lin >> 2, u = lin & 3;
        uint32_t dst = sm + r * 64 + ((u ^ ((r >> 1) & 3)) * 16);
        const bf* src = g + (size_t)r * ld + u * 8;
        asm volatile("cp.async.cg.shared.global [%0], [%1], 16;" :: "r"(dst), "l"(src));
    }
}

template <bool DIAG>
__device__ __forceinline__ void issue_stage(uint32_t sbase,
    const bf* gAh, const bf* gAl, const bf* gBh, const bf* gBl,
    size_t ld, int ch, int tid) {
    load_tile_sw(sbase + 0 * TILE_BYT, gAh + (size_t)ch * KC, ld, tid);
    load_tile_sw(sbase + 1 * TILE_BYT, gAl + (size_t)ch * KC, ld, tid);
    if (!DIAG) {
        load_tile_sw(sbase + 2 * TILE_BYT, gBh + (size_t)ch * KC, ld, tid);
        load_tile_sw(sbase + 3 * TILE_BYT, gBl + (size_t)ch * KC, ld, tid);
    }
    asm volatile("cp.async.commit_group;");
}

template <bool DIAG>
__device__ __forceinline__ void mma_pipeline(uint32_t ubase, int nch,
    const bf* gAh, const bf* gAl, const bf* gBh, const bf* gBl, size_t ld,
    int tid, int warp_m, int warp_n, float c[4][4][4]) {
    const uint32_t STG = (DIAG ? 2 : 4) * TILE_BYT;
    const int lane = tid & 31;
    uint32_t a_off[2], b_off[2];
    {
        const int sw  = (lane >> 1) & 3;
        const int l15 = lane & 15;
        const int rit = ((lane >> 4) << 3) + (lane & 7);
#pragma unroll
        for (int ks = 0; ks < 2; ks++) {
            a_off[ks] = (uint32_t)l15 * 64 + (uint32_t)(((ks * 2 + (lane >> 4)) ^ sw) * 16);
            b_off[ks] = (uint32_t)rit * 64 + (uint32_t)(((ks * 2 + ((lane >> 3) & 1)) ^ sw) * 16);
        }
    }

    issue_stage<DIAG>(ubase + 0 * STG, gAh, gAl, gBh, gBl, ld, 0, tid);
    issue_stage<DIAG>(ubase + 1 * STG, gAh, gAl, gBh, gBl, ld, 1, tid);

    int st = 0;
    for (int ch = 0; ch < nch; ch++) {
        if (ch < nch - 1) { asm volatile("cp.async.wait_group 1;"); }
        else              { asm volatile("cp.async.wait_group 0;"); }
        __syncthreads();
        if (ch + 2 < nch) {
            int st2 = st + 2; if (st2 >= 3) st2 -= 3;
            issue_stage<DIAG>(ubase + (uint32_t)st2 * STG,
                              gAh, gAl, gBh, gBl, ld, ch + 2, tid);
        }

        const uint32_t uAh = ubase + (uint32_t)st * STG;
        const uint32_t uAl = uAh + TILE_BYT;
        const uint32_t uBh = DIAG ? uAh : (uAh + 2 * TILE_BYT);
        const uint32_t uBl = DIAG ? uAl : (uAh + 3 * TILE_BYT);
#pragma unroll
        for (int ks = 0; ks < 2; ks++) {
            uint32_t ah[4][4], al[4][4], bh[4][2], bl[4][2];
#pragma unroll
            for (int mt = 0; mt < 4; mt++) {
                uint32_t ra = (uint32_t)(warp_m + mt * 16) * 64;
                ldsm_x4(ah[mt], uAh + ra + a_off[ks]);
                ldsm_x4(al[mt], uAl + ra + a_off[ks]);
            }
#pragma unroll
            for (int nt2 = 0; nt2 < 2; nt2++) {
                uint32_t rb = (uint32_t)(warp_n + nt2 * 16) * 64;
                uint32_t t0[4], t1[4];
                ldsm_x4(t0, uBh + rb + b_off[ks]);
                ldsm_x4(t1, uBl + rb + b_off[ks]);
                bh[nt2 * 2][0] = t0[0]; bh[nt2 * 2][1] = t0[1];
                bh[nt2 * 2 + 1][0] = t0[2]; bh[nt2 * 2 + 1][1] = t0[3];
                bl[nt2 * 2][0] = t1[0]; bl[nt2 * 2][1] = t1[1];
                bl[nt2 * 2 + 1][0] = t1[2]; bl[nt2 * 2 + 1][1] = t1[3];
            }
#pragma unroll
            for (int mt = 0; mt < 4; mt++)
#pragma unroll
                for (int nt = 0; nt < 4; nt++) mma_bf16(c[mt][nt], ah[mt], bh[nt]);
#pragma unroll
            for (int mt = 0; mt < 4; mt++)
#pragma unroll
                for (int nt = 0; nt < 4; nt++) mma_bf16(c[mt][nt], ah[mt], bl[nt]);
#pragma unroll
            for (int mt = 0; mt < 4; mt++)
#pragma unroll
                for (int nt = 0; nt < 4; nt++) mma_bf16(c[mt][nt], al[mt], bh[nt]);
        }
        if (++st == 3) st = 0;
    }
    __syncthreads();
}

// ---------------- K4: G partials ----------------
__global__ __launch_bounds__(256, 2)
void gemmG(const bf* __restrict__ xch, const bf* __restrict__ xcl,
           float* __restrict__ Gp) {
    extern __shared__ __align__(16) char dyn[];
    const uint32_t ubase = smem_u32(dyn);
    const int tile = blockIdx.x;
    const int e0 = (tile == 2) ? 128 : 0;
    const int f0 = (tile == 0) ? 0 : 128;
    const bool diag = (tile != 1);
    const int s = blockIdx.y;
    const int b = blockIdx.z;
    const int start = 21 * s + (s > 4 ? s - 4 : 0);
    const int nch   = (s < 4) ? 21 : 22;
    const int tid = threadIdx.x, wid = tid >> 5, lane = tid & 31;
    const int warp_m = (wid & 1) * 64, warp_n = (wid >> 1) * 32;

    float c[4][4][4];
#pragma unroll
    for (int i = 0; i < 4; i++)
#pragma unroll
        for (int j = 0; j < 4; j++)
#pragma unroll
            for (int q = 0; q < 4; q++) c[i][j][q] = 0.f;

    const size_t noff = (size_t)start * KC;
    const bf* gAh = xch + ((size_t)b * 256 + e0) * HWP + noff;
    const bf* gAl = xcl + ((size_t)b * 256 + e0) * HWP + noff;
    const bf* gBh = xch + ((size_t)b * 256 + f0) * HWP + noff;
    const bf* gBl = xcl + ((size_t)b * 256 + f0) * HWP + noff;

    if (diag)
        mma_pipeline<true>(ubase, nch, gAh, gAl, gBh, gBl, HWP, tid, warp_m, warp_n, c);
    else
        mma_pipeline<false>(ubase, nch, gAh, gAl, gBh, gBl, HWP, tid, warp_m, warp_n, c);

    const int g = lane >> 2, t = lane & 3;
    float* dst = Gp + (size_t)(b * 6 + s) * 65536;
#pragma unroll
    for (int mt = 0; mt < 4; mt++)
#pragma unroll
        for (int nt = 0; nt < 4; nt++) {
            int f = f0 + warp_n + nt * 8 + 2 * t;
#pragma unroll
            for (int half = 0; half < 2; half++) {
                int e = e0 + warp_m + mt * 16 + g + half * 8;
                *(float2*)&dst[(size_t)e * 256 + f] =
                    make_float2(c[mt][nt][half * 2 + 0], c[mt][nt][half * 2 + 1]);
            }
        }
}

// ---------------- K5: reduceG ----------------
__global__ __launch_bounds__(256)
void reduceG(const float* __restrict__ Gp, float* __restrict__ G) {
    __shared__ float tile[64][65];
    const int bt = blockIdx.x;
    const int b  = blockIdx.y;
    const int eT = bt >> 2, fT = bt & 3;
    const int e0 = eT * 64, f0 = fT * 64;
    const bool mirror = (e0 >= 128) && (f0 < 128);
    const int tid = threadIdx.x;
    float4 acc[4];
    int rr[4], cc4[4];
#pragma unroll
    for (int i = 0; i < 4; i++) {
        int lin = tid + i * 256;
        rr[i] = lin >> 4; cc4[i] = (lin & 15) * 4;
        acc[i] = make_float4(0.f, 0.f, 0.f, 0.f);
    }
#pragma unroll
    for (int z = 0; z < 6; z++) {
        const float* s = Gp + ((size_t)(b * 6 + z)) * 65536;
#pragma unroll
        for (int i = 0; i < 4; i++) {
            int sr = mirror ? (f0 + rr[i]) : (e0 + rr[i]);
            int sc = mirror ? (e0 + cc4[i]) : (f0 + cc4[i]);
            float4 v = *(const float4*)&s[(size_t)sr * 256 + sc];
            acc[i].x += v.x; acc[i].y += v.y; acc[i].z += v.z; acc[i].w += v.w;
        }
    }
    float* dst = G + (size_t)b * 65536;
    if (!mirror) {
#pragma unroll
        for (int i = 0; i < 4; i++)
            *(float4*)&dst[(size_t)(e0 + rr[i]) * 256 + f0 + cc4[i]] = acc[i];
    } else {
#pragma unroll
        for (int i = 0; i < 4; i++) {
            tile[rr[i]][cc4[i] + 0] = acc[i].x;
            tile[rr[i]][cc4[i] + 1] = acc[i].y;
            tile[rr[i]][cc4[i] + 2] = acc[i].z;
            tile[rr[i]][cc4[i] + 3] = acc[i].w;
        }
        __syncthreads();
#pragma unroll
        for (int i = 0; i < 4; i++) {
            int r = rr[i], c4 = cc4[i];
            float4 o = make_float4(tile[c4 + 0][r], tile[c4 + 1][r],
                                   tile[c4 + 2][r], tile[c4 + 3][r]);
            *(float4*)&dst[(size_t)(e0 + r) * 256 + f0 + c4] = o;
        }
    }
}

// ---------------- K6: gemmU ----------------
__global__ __launch_bounds__(256)
void gemmU(const float* __restrict__ Wq, const float* __restrict__ G,
           float* __restrict__ U) {
    __shared__ float As[16][68];
    __shared__ float Bs[16][68];
    const int i0 = blockIdx.x * 64, j0 = blockIdx.y * 64, b = blockIdx.z;
    const int tid = threadIdx.x, ty = tid >> 4, tx = tid & 15;
    const float* Gb = G + (size_t)b * 65536;
    float acc[4][4] = {};
    for (int k0 = 0; k0 < 256; k0 += 16) {
        {
            int i = tid >> 2, k4 = (tid & 3) * 4;
            float4 a = *(const float4*)&Wq[(size_t)(i0 + i) * 256 + k0 + k4];
            As[k4 + 0][i] = a.x; As[k4 + 1][i] = a.y;
            As[k4 + 2][i] = a.z; As[k4 + 3][i] = a.w;
            int k = tid >> 4, j4 = (tid & 15) * 4;
            *(float4*)&Bs[k][j4] = *(const float4*)&Gb[(size_t)(k0 + k) * 256 + j0 + j4];
        }
        __syncthreads();
#pragma unroll
        for (int k = 0; k < 16; k++) {
            float a[4], bb[4];
#pragma unroll
            for (int x = 0; x < 4; x++) a[x] = As[k][ty * 4 + x];
#pragma unroll
            for (int x = 0; x < 4; x++) bb[x] = Bs[k][tx * 4 + x];
#pragma unroll
            for (int ii = 0; ii < 4; ii++)
#pragma unroll
                for (int jj = 0; jj < 4; jj++) acc[ii][jj] += a[ii] * bb[jj];
        }
        __syncthreads();
    }
#pragma unroll
    for (int ii = 0; ii < 4; ii++)
        *(float4*)&U[((size_t)b * 256 + i0 + ty * 4 + ii) * 256 + j0 + tx * 4] =
            make_float4(acc[ii][0], acc[ii][1], acc[ii][2], acc[ii][3]);
}

// ---------------- K7: gemmMAN ----------------
__global__ __launch_bounds__(256)
void gemmMAN(const float* __restrict__ qkv_w, const float* __restrict__ XC,
             float* __restrict__ MN) {
    __shared__ float Ws[32][36];
    __shared__ float XCs[32][132];
    const int r0 = blockIdx.x * 32;
    const int b  = blockIdx.y;
    const int tid = threadIdx.x;
    const int w   = tid >> 5;
    const int lane = tid & 31;
    float acc[4][5];
#pragma unroll
    for (int i = 0; i < 4; i++)
#pragma unroll
        for (int cg = 0; cg < 5; cg++) acc[i][cg] = 0.f;
    const bool has5 = (lane < 4);

    for (int k0 = 0; k0 < 256; k0 += 32) {
        {
            int r = tid >> 3, k4 = (tid & 7) * 4;
            *(float4*)&Ws[r][k4] = *(const float4*)&qkv_w[(size_t)(r0 + r) * 256 + k0 + k4];
        }
#pragma unroll
        for (int it = 0; it < 5; it++) {
            int f4 = tid + it * 256;
            if (f4 < 1056) {
                int k = f4 / 33, g = f4 % 33;
                *(float4*)&XCs[k][g * 4] =
                    *(const float4*)&XC[((size_t)b * 256 + k0 + k) * 132 + g * 4];
            }
        }
        __syncthreads();
#pragma unroll 4
        for (int k = 0; k < 32; k++) {
            float xv[5];
#pragma unroll
            for (int cg = 0; cg < 4; cg++) xv[cg] = XCs[k][lane + 32 * cg];
            xv[4] = has5 ? XCs[k][lane + 128] : 0.f;
#pragma unroll
            for (int i = 0; i < 4; i++) {
                float wv = Ws[w * 4 + i][k];
#pragma unroll
                for (int cg = 0; cg < 5; cg++) acc[i][cg] += wv * xv[cg];
            }
        }
        __syncthreads();
    }
#pragma unroll
    for (int i = 0; i < 4; i++) {
        float* dst = MN + ((size_t)b * 512 + r0 + w * 4 + i) * 132;
#pragma unroll
        for (int cg = 0; cg < 4; cg++) dst[lane + 32 * cg] = acc[i][cg];
        if (has5) dst[lane + 128] = acc[i][4];
    }
}

// ---------------- K8: assembly ----------------
#define SKS 257
#define SPS 133
__global__ __launch_bounds__(256)
void assembly(const float* __restrict__ U, const float* __restrict__ qkv_w,
              const float* __restrict__ qkv_b, const float* __restrict__ MN,
              const float* __restrict__ Pq, const float* __restrict__ Pk,
              const float* __restrict__ Pk2,
              const float* __restrict__ mod_mult, const float* __restrict__ mod_bias,
              bf* __restrict__ weh, bf* __restrict__ wel, float* __restrict__ cb) {
    extern __shared__ float sm[];
    float* sU  = sm;
    float* sK  = sU + 32 * SKS;
    float* sMA = sK + 32 * SKS;
    float* sPq = sMA + 32 * SPS;
    float* sPk = sPq + 32 * SPS;
    float* sNB2 = sPk + 32 * SPS;
    float* sL  = sNB2 + 32 * SPS;
    const int h = blockIdx.x, b = blockIdx.y;
    const int ch0 = h * 32;
    const int tid = threadIdx.x;

    for (int i = tid; i < 32 * 256; i += 256) {
        int r = i >> 8, e = i & 255;
        sU[r * SKS + e] = U[((size_t)b * 256 + ch0 + r) * 256 + e];
        sK[r * SKS + e] = qkv_w[(size_t)(256 + ch0 + r) * 256 + e];
    }
    for (int i = tid; i < 32 * 132; i += 256) {
        int r = i / 132, j = i % 132;
        sMA[r * SPS + j]  = MN[((size_t)b * 512 + ch0 + r) * 132 + j];
        sNB2[r * SPS + j] = MN[((size_t)b * 512 + 256 + ch0 + r) * 132 + j]
                          + Pk2[(ch0 + r) * 132 + j];
        sPq[r * SPS + j]  = Pq[(ch0 + r) * 132 + j];
        sPk[r * SPS + j]  = Pk[(ch0 + r) * 132 + j];
    }
    __syncthreads();

    const int d = tid & 31, cw = tid >> 5;
    {
        float l0[4] = {0,0,0,0}, dt1[4] = {0,0,0,0}, dt2[4] = {0,0,0,0};
        for (int e = 0; e < 256; e++) {
            float kv = sK[d * SKS + e];
#pragma unroll
            for (int k = 0; k < 4; k++) l0[k] += sU[(8 * k + cw) * SKS + e] * kv;
        }
        for (int j = 0; j < 132; j++) {
            float pk = sPk[d * SPS + j], nb = sNB2[d * SPS + j];
#pragma unroll
            for (int k = 0; k < 4; k++) {
                int c = 8 * k + cw;
                dt1[k] += sMA[c * SPS + j] * pk;
                dt2[k] += sPq[c * SPS + j] * nb;
            }
        }
        float sv = sNB2[d * SPS + 128];
#pragma unroll
        for (int k = 0; k < 4; k++) {
            int c = 8 * k + cw;
            float mm = mod_mult[b * 256 + ch0 + c], mb = mod_bias[b * 256 + ch0 + c];
            sL[c * 33 + d] = mm * (l0[k] + dt1[k] + dt2[k]) + mb * sv;
        }
    }
    __syncthreads();

    {
        int w = tid >> 5, lane = tid & 31;
        const float rs = 0.17677669529663687f;
#pragma unroll
        for (int r = w * 4; r < w * 4 + 4; r++) {
            float v = sL[r * 33 + lane] * rs;
            float mx = v;
#pragma unroll
            for (int o = 16; o; o >>= 1) mx = fmaxf(mx, __shfl_xor_sync(0xffffffffu, mx, o));
            float e = expf(v - mx);
            float s = e;
#pragma unroll
            for (int o = 16; o; o >>= 1) s += __shfl_xor_sync(0xffffffffu, s, o);
            sL[r * 33 + lane] = e / s;
        }
    }
    __syncthreads();

    float* sV = sU;
    for (int i = tid; i < 32 * 64; i += 256) {
        int r = i >> 6, e4 = (i & 63) * 4;
        *(float4*)&sV[r * 256 + e4] =
            *(const float4*)&qkv_w[(size_t)(512 + ch0 + r) * 256 + e4];
    }
    __syncthreads();

    {
        int lane = tid & 31, w = tid >> 5;
        float wrow[32];
#pragma unroll
        for (int dd = 0; dd < 32; dd++) wrow[dd] = sL[lane * 33 + dd];
        for (int i = 0; i < 32; i++) {
            int e = w * 32 + i;
            float acc = 0.f;
#pragma unroll
            for (int dd = 0; dd < 32; dd++) acc += wrow[dd] * sV[dd * 256 + e];
            bf hi = __float2bfloat16(acc);
            bf lo = __float2bfloat16(acc - __bfloat162float(hi));
            size_t idx = ((size_t)b * 256 + ch0 + lane) * 256 + e;
            weh[idx] = hi; wel[idx] = lo;
        }
        if (tid < 32) {
            float acc = 0.f;
            for (int dd = 0; dd < 32; dd++) acc += sL[tid * 33 + dd] * qkv_b[512 + ch0 + dd];
            cb[b * 256 + ch0 + tid] = acc;
        }
    }
}

// ---------------- K9: out_gemm — B loaded from e-major xch/xcl via ldsm.trans ----------------
// B tile: 32 e-rows x 256B (128 p), swizzle u' = (u&8)|((u&7)^(r&7))
__device__ __forceinline__ void load_tileB_tr(uint32_t sm, const bf* g, int tid) {
#pragma unroll
    for (int ii = 0; ii < 2; ii++) {
        int lin = tid + ii * 256;            // 0..511
        int r = lin >> 4, u = lin & 15;      // r = e-row 0..31, u = 16B unit
        int u2 = (u & 8) | ((u & 7) ^ (r & 7));
        uint32_t dst = sm + r * 256 + u2 * 16;
        const bf* src = g + (size_t)r * HWP + u * 8;
        asm volatile("cp.async.cg.shared.global [%0], [%1], 16;" :: "r"(dst), "l"(src));
    }
}

__device__ __forceinline__ void issue_stage_og(uint32_t sbase,
    const bf* gAh, const bf* gAl, const bf* gBh, const bf* gBl, int ch, int tid) {
    load_tile_sw(sbase + 0 * TILE_BYT, gAh + (size_t)ch * KC, 256, tid);
    load_tile_sw(sbase + 1 * TILE_BYT, gAl + (size_t)ch * KC, 256, tid);
    load_tileB_tr(sbase + 2 * TILE_BYT, gBh + (size_t)(ch * KC) * HWP, tid);
    load_tileB_tr(sbase + 3 * TILE_BYT, gBl + (size_t)(ch * KC) * HWP, tid);
    asm volatile("cp.async.commit_group;");
}

__global__ __launch_bounds__(256, 2)
void out_gemm(const bf* __restrict__ weh, const bf* __restrict__ wel,
              const bf* __restrict__ xch, const bf* __restrict__ xcl,
              const float* __restrict__ cb, float* __restrict__ out) {
    extern __shared__ __align__(16) char dyn[];
    const uint32_t ubase = smem_u32(dyn);
    const int p0 = blockIdx.x * 128;
    const int o0 = blockIdx.y * 128;
    const int b  = blockIdx.z;
    const int tid = threadIdx.x, wid = tid >> 5, lane = tid & 31;
    const int warp_m = (wid & 1) * 64, warp_n = (wid >> 1) * 32;

    float c[4][4][4];
#pragma unroll
    for (int i = 0; i < 4; i++)
#pragma unroll
        for (int j = 0; j < 4; j++)
#pragma unroll
            for (int q = 0; q < 4; q++) c[i][j][q] = 0.f;

    // A ldsm offsets (64B rows, same swizzle as gemmG)
    uint32_t a_off[2];
    // B trans ldsm offsets [ks][nt2]
    uint32_t b_offT[2][2];
    {
        const int sw  = (lane >> 1) & 3;
        const int l15 = lane & 15;
#pragma unroll
        for (int ks = 0; ks < 2; ks++)
            a_off[ks] = (uint32_t)l15 * 64 + (uint32_t)(((ks * 2 + (lane >> 4)) ^ sw) * 16);
        const int hi   = lane >> 4;          // p +8 half
        const int row8 = ((lane >> 3) & 1) * 8;  // k +8 half
        const int l7   = lane & 7;
#pragma unroll
        for (int ks = 0; ks < 2; ks++)
#pragma unroll
            for (int nt2 = 0; nt2 < 2; nt2++) {
                int rloc = ks * 16 + row8 + l7;           // e row in tile
                int u    = (warp_n >> 3) + 2 * nt2 + hi;  // 16B unit (p/8)
                int u2   = (u & 8) | ((u & 7) ^ l7);
                b_offT[ks][nt2] = (uint32_t)rloc * 256 + (uint32_t)u2 * 16;
            }
    }

    const bf* gAh = weh + ((size_t)b * 256 + o0) * 256;
    const bf* gAl = wel + ((size_t)b * 256 + o0) * 256;
    const bf* gBh = xch + (size_t)b * 256 * HWP + p0;
    const bf* gBl = xcl + (size_t)b * 256 * HWP + p0;

    issue_stage_og(ubase + 0 * 4 * TILE_BYT, gAh, gAl, gBh, gBl, 0, tid);
    issue_stage_og(ubase + 1 * 4 * TILE_BYT, gAh, gAl, gBh, gBl, 1, tid);

    int st = 0;
    for (int ch = 0; ch < 8; ch++) {
        if (ch < 7) { asm volatile("cp.async.wait_group 1;"); }
        else        { asm volatile("cp.async.wait_group 0;"); }
        __syncthreads();
        if (ch + 2 < 8) {
            int st2 = st + 2; if (st2 >= 3) st2 -= 3;
            issue_stage_og(ubase + (uint32_t)st2 * 4 * TILE_BYT, gAh, gAl, gBh, gBl, ch + 2, tid);
        }

        const uint32_t uAh = ubase + (uint32_t)st * 4 * TILE_BYT;
        const uint32_t uAl = uAh + TILE_BYT;
        const uint32_t uBh = uAh + 2 * TILE_BYT;
        const uint32_t uBl = uAh + 3 * TILE_BYT;
#pragma unroll
        for (int ks = 0; ks < 2; ks++) {
            uint32_t ah[4][4], al[4][4], bh[4][2], bl[4][2];
#pragma unroll
            for (int mt = 0; mt < 4; mt++) {
                uint32_t ra = (uint32_t)(warp_m + mt * 16) * 64;
                ldsm_x4(ah[mt], uAh + ra + a_off[ks]);
                ldsm_x4(al[mt], uAl + ra + a_off[ks]);
            }
#pragma unroll
            for (int nt2 = 0; nt2 < 2; nt2++) {
                uint32_t t0[4], t1[4];
                ldsm_x4_tr(t0, uBh + b_offT[ks][nt2]);
                ldsm_x4_tr(t1, uBl + b_offT[ks][nt2]);
                bh[nt2 * 2][0] = t0[0]; bh[nt2 * 2][1] = t0[1];
                bh[nt2 * 2 + 1][0] = t0[2]; bh[nt2 * 2 + 1][1] = t0[3];
                bl[nt2 * 2][0] = t1[0]; bl[nt2 * 2][1] = t1[1];
                bl[nt2 * 2 + 1][0] = t1[2]; bl[nt2 * 2 + 1][1] = t1[3];
            }
#pragma unroll
            for (int mt = 0; mt < 4; mt++)
#pragma unroll
                for (int nt = 0; nt < 4; nt++) mma_bf16(c[mt][nt], ah[mt], bh[nt]);
#pragma unroll
            for (int mt = 0; mt < 4; mt++)
#pragma unroll
                for (int nt = 0; nt < 4; nt++) mma_bf16(c[mt][nt], ah[mt], bl[nt]);
#pragma unroll
            for (int mt = 0; mt < 4; mt++)
#pragma unroll
                for (int nt = 0; nt < 4; nt++) mma_bf16(c[mt][nt], al[mt], bh[nt]);
        }
        if (++st == 3) st = 0;
    }
    __syncthreads();

    const int g = lane >> 2, t = lane & 3;
#pragma unroll
    for (int mt = 0; mt < 4; mt++)
#pragma unroll
        for (int nt = 0; nt < 4; nt++) {
            int p = p0 + warp_n + nt * 8 + 2 * t;
#pragma unroll
            for (int half = 0; half < 2; half++) {
                int o = o0 + warp_m + mt * 16 + g + half * 8;
                float add = cb[b * 256 + o];
                *(float2*)(out + ((size_t)b * 512 + 256 + o) * HWP + p) =
                    make_float2(c[mt][nt][half * 2 + 0] + add,
                                c[mt][nt][half * 2 + 1] + add);
            }
        }
}

// ---------------- launcher (round-13 two-stream DAG) ----------------
extern "C" void kernel_launch(void* const* d_in, const int* in_sizes, int n_in,
                              void* d_out, int out_size) {
    const float* x        = (const float*)d_in[0];
    const float* mod_mult = (const float*)d_in[1];
    const float* mod_bias = (const float*)d_in[2];
    const float* qkv_w    = (const float*)d_in[3];
    const float* qkv_b    = (const float*)d_in[4];
    const float* pe_q_h   = (const float*)d_in[5];
    const float* pe_q_w   = (const float*)d_in[6];
    const float* pe_k_h   = (const float*)d_in[7];
    const float* pe_k_w   = (const float*)d_in[8];
    const float* pab      = (const float*)d_in[9];
    const float* pqb      = (const float*)d_in[10];
    float* out = (float*)d_out;

    bf *xch, *xcl, *weh, *wel;
    float *XC, *Gp, *G, *U, *MN, *Pq, *Pk, *Pk2, *cb;
    cudaGetSymbolAddress((void**)&xch, g_xch);
    cudaGetSymbolAddress((void**)&xcl, g_xcl);
    cudaGetSymbolAddress((void**)&XC, g_XC);
    cudaGetSymbolAddress((void**)&Gp, g_Gp);
    cudaGetSymbolAddress((void**)&G, g_G);
    cudaGetSymbolAddress((void**)&U, g_U);
    cudaGetSymbolAddress((void**)&MN, g_MN);
    cudaGetSymbolAddress((void**)&Pq, g_Pq);
    cudaGetSymbolAddress((void**)&Pk, g_Pk);
    cudaGetSymbolAddress((void**)&Pk2, g_Pk2);
    cudaGetSymbolAddress((void**)&weh, g_weh);
    cudaGetSymbolAddress((void**)&wel, g_wel);
    cudaGetSymbolAddress((void**)&cb, g_cb);

    static cudaStream_t s1 = nullptr;
    static cudaEvent_t evStart = nullptr, evSilu = nullptr, evSide = nullptr;
    if (s1 == nullptr) {
        cudaStreamCreateWithFlags(&s1, cudaStreamNonBlocking);
        cudaEventCreateWithFlags(&evStart, cudaEventDisableTiming);
        cudaEventCreateWithFlags(&evSilu, cudaEventDisableTiming);
        cudaEventCreateWithFlags(&evSide, cudaEventDisableTiming);
        cudaFuncSetAttribute(gemmG, cudaFuncAttributeMaxDynamicSharedMemorySize, GSMEM);
        cudaFuncSetAttribute(out_gemm, cudaFuncAttributeMaxDynamicSharedMemorySize, GSMEM);
        cudaFuncSetAttribute(assembly, cudaFuncAttributeMaxDynamicSharedMemorySize, 140000);
    }

    // fork: side stream starts with prepP (no deps)
    cudaEventRecord(evStart, 0);
    cudaStreamWaitEvent(s1, evStart, 0);
    prepP<<<256, 64, 0, s1>>>(qkv_b, pe_q_h, pe_q_w, pe_k_h, pe_k_w, Pq, Pk, Pk2);

    // main: silu (single pass)
    silu_split_kernel<<<4096, 256>>>(x, pab, pqb, out, xch, xcl);
    cudaEventRecord(evSilu, 0);

    // side: reduceX -> gemmMAN
    cudaStreamWaitEvent(s1, evSilu, 0);
    reduceX<<<dim3(256, 16), 256, 0, s1>>>(out, pqb, XC);
    gemmMAN<<<dim3(16, 16), 256, 0, s1>>>(qkv_w, XC, MN);
    cudaEventRecord(evSide, s1);

    // main: gemmG -> reduceG -> gemmU
    gemmG<<<dim3(3, 6, 16), 256, GSMEM>>>(xch, xcl, Gp);
    reduceG<<<dim3(16, 16), 256>>>(Gp, G);
    gemmU<<<dim3(4, 4, 16), 256>>>(qkv_w, G, U);

    // join: assembly needs MN (side) + U (main)
    cudaStreamWaitEvent(0, evSide, 0);
    assembly<<<dim3(8, 16), 256, 140000>>>(U, qkv_w, qkv_b, MN, Pq, Pk, Pk2,
                                           mod_mult, mod_bias, weh, wel, cb);
    out_gemm<<<dim3(32, 2, 16), 256, GSMEM>>>(weh, wel, xch, xcl, cb, out);
}